// round 1
// baseline (speedup 1.0000x reference)
#include <cuda_runtime.h>
#include <cuda_bf16.h>
#include <math.h>

#define BB 2
#define SS 2048
#define DD 1024
#define NH 16
#define HD 64
#define MM (BB*SS)

// Scratch (device globals: allocation-free rule)
__device__ float g_q[(size_t)BB*NH*SS*HD];
__device__ float g_k[(size_t)BB*NH*SS*HD];
__device__ float g_v[(size_t)BB*NH*SS*HD];
__device__ float g_att[(size_t)MM*DD];

// ---------------------------------------------------------------------------
// Kernel 1: fused QKV GEMM (x @ {wq,wk,wv}) + RoPE epilogue, scatter to
// (b,h,s,d) layout. 128x128 tile, BK=8, 256 threads, 8x8 per thread.
// grid = (24, 32): bx/8 selects weight, bx%8 selects 128-col tile.
// ---------------------------------------------------------------------------
__global__ __launch_bounds__(256) void qkv_gemm_kernel(
    const float* __restrict__ x, const float* __restrict__ wq,
    const float* __restrict__ wk, const float* __restrict__ wv)
{
    __shared__ float As[8][132];
    __shared__ float Bs[8][128];
    const int bx = blockIdx.x;
    const int which = bx >> 3;             // 0=q, 1=k, 2=v
    const int n0 = (bx & 7) << 7;
    const int m0 = blockIdx.y << 7;
    const float* wmat = (which == 0) ? wq : (which == 1) ? wk : wv;
    const int tid = threadIdx.x;
    const int tx = tid & 15, ty = tid >> 4;

    float acc[8][8];
#pragma unroll
    for (int i = 0; i < 8; i++)
#pragma unroll
        for (int j = 0; j < 8; j++) acc[i][j] = 0.f;

    const int ar = tid >> 1, ac = (tid & 1) << 2;   // A: 128 rows x 8 k
    const int br = tid >> 5, bc = (tid & 31) << 2;  // B: 8 k x 128 cols

    for (int k0 = 0; k0 < DD; k0 += 8) {
        float4 av = *reinterpret_cast<const float4*>(x + (size_t)(m0 + ar) * DD + k0 + ac);
        float4 bv = *reinterpret_cast<const float4*>(wmat + (size_t)(k0 + br) * DD + n0 + bc);
        As[ac + 0][ar] = av.x; As[ac + 1][ar] = av.y;
        As[ac + 2][ar] = av.z; As[ac + 3][ar] = av.w;
        *reinterpret_cast<float4*>(&Bs[br][bc]) = bv;
        __syncthreads();
#pragma unroll
        for (int kk = 0; kk < 8; kk++) {
            float a[8], b[8];
            float4 a0 = *reinterpret_cast<const float4*>(&As[kk][ty * 8]);
            float4 a1 = *reinterpret_cast<const float4*>(&As[kk][ty * 8 + 4]);
            a[0]=a0.x; a[1]=a0.y; a[2]=a0.z; a[3]=a0.w;
            a[4]=a1.x; a[5]=a1.y; a[6]=a1.z; a[7]=a1.w;
            float4 b0 = *reinterpret_cast<const float4*>(&Bs[kk][tx * 8]);
            float4 b1 = *reinterpret_cast<const float4*>(&Bs[kk][tx * 8 + 4]);
            b[0]=b0.x; b[1]=b0.y; b[2]=b0.z; b[3]=b0.w;
            b[4]=b1.x; b[5]=b1.y; b[6]=b1.z; b[7]=b1.w;
#pragma unroll
            for (int i = 0; i < 8; i++)
#pragma unroll
                for (int j = 0; j < 8; j++)
                    acc[i][j] = fmaf(a[i], b[j], acc[i][j]);
        }
        __syncthreads();
    }

    // Epilogue: RoPE for q,k; scatter to (b,h,s,d)
    float* dst = (which == 0) ? g_q : (which == 1) ? g_k : g_v;
#pragma unroll
    for (int i = 0; i < 8; i++) {
        const int m = m0 + ty * 8 + i;
        const int b = m / SS, s = m % SS;
#pragma unroll
        for (int j = 0; j < 8; j += 2) {
            const int col = n0 + tx * 8 + j;     // even
            const int h = col >> 6, d = col & 63; // d even
            float v0 = acc[i][j], v1 = acc[i][j + 1];
            if (which < 2) {
                // inv_freq = 10000^(-d/64); angle rounded to fp32 like reference
                float inv = expf(-0.14391156516f * (float)d);
                float ang = (float)s * inv;
                float sn, cs;
                sincosf(ang, &sn, &cs);
                float r0 = v0 * cs - v1 * sn;
                float r1 = v0 * sn + v1 * cs;
                v0 = r0; v1 = r1;
            }
            size_t base = (((size_t)(b * NH + h)) * SS + s) * HD + d;
            dst[base] = v0;
            dst[base + 1] = v1;
        }
    }
}

// ---------------------------------------------------------------------------
// Kernel 2: causal flash attention, fp32. One CTA = (64 q rows) x (b,h).
// 256 threads as 16x16, 4x4 micro-tiles. Dynamic smem.
// ---------------------------------------------------------------------------
__global__ __launch_bounds__(256) void attn_kernel()
{
    extern __shared__ float sm[];
    float* Qs = sm;                 // [64][68] transposed: Qs[d][m]
    float* Ks = Qs + 64 * 68;       // [64][68] transposed: Ks[d][c]
    float* Ps = Ks + 64 * 68;       // [64][68] Ps[r][c]
    float* Vs = Ps + 64 * 68;       // [64][64] Vs[c][d]

    const int qt = blockIdx.x;      // 0..31
    const int bh = blockIdx.y;      // 0..31
    const int tid = threadIdx.x;
    const int tx = tid & 15, ty = tid >> 4;
    const float* qp = g_q + (size_t)bh * SS * HD;
    const float* kp = g_k + (size_t)bh * SS * HD;
    const float* vp = g_v + (size_t)bh * SS * HD;

    // load Q tile transposed
    for (int it = tid; it < 1024; it += 256) {
        int r = it >> 4, c4 = (it & 15) << 2;
        float4 v = *reinterpret_cast<const float4*>(qp + (size_t)(qt * 64 + r) * HD + c4);
        Qs[(c4 + 0) * 68 + r] = v.x; Qs[(c4 + 1) * 68 + r] = v.y;
        Qs[(c4 + 2) * 68 + r] = v.z; Qs[(c4 + 3) * 68 + r] = v.w;
    }

    float o[4][4];
    float mrow[4], lrow[4];
#pragma unroll
    for (int i = 0; i < 4; i++) {
        mrow[i] = -INFINITY; lrow[i] = 0.f;
#pragma unroll
        for (int j = 0; j < 4; j++) o[i][j] = 0.f;
    }

    for (int kt = 0; kt <= qt; kt++) {
        __syncthreads();
        // load K tile (transposed) and V tile
        for (int it = tid; it < 1024; it += 256) {
            int r = it >> 4, c4 = (it & 15) << 2;
            float4 kv = *reinterpret_cast<const float4*>(kp + (size_t)(kt * 64 + r) * HD + c4);
            Ks[(c4 + 0) * 68 + r] = kv.x; Ks[(c4 + 1) * 68 + r] = kv.y;
            Ks[(c4 + 2) * 68 + r] = kv.z; Ks[(c4 + 3) * 68 + r] = kv.w;
            float4 vv = *reinterpret_cast<const float4*>(vp + (size_t)(kt * 64 + r) * HD + c4);
            *reinterpret_cast<float4*>(&Vs[r * 64 + c4]) = vv;
        }
        __syncthreads();

        // S = Q K^T (64x64), each thread 4x4
        float sv[4][4];
#pragma unroll
        for (int i = 0; i < 4; i++)
#pragma unroll
            for (int j = 0; j < 4; j++) sv[i][j] = 0.f;
#pragma unroll 8
        for (int kk = 0; kk < 64; kk++) {
            float4 a = *reinterpret_cast<const float4*>(Qs + kk * 68 + ty * 4);
            float4 bq = *reinterpret_cast<const float4*>(Ks + kk * 68 + tx * 4);
            float af[4] = {a.x, a.y, a.z, a.w};
            float bf[4] = {bq.x, bq.y, bq.z, bq.w};
#pragma unroll
            for (int i = 0; i < 4; i++)
#pragma unroll
                for (int j = 0; j < 4; j++)
                    sv[i][j] = fmaf(af[i], bf[j], sv[i][j]);
        }
        // scale + causal mask
#pragma unroll
        for (int i = 0; i < 4; i++)
#pragma unroll
            for (int j = 0; j < 4; j++) {
                sv[i][j] *= 0.125f;
                if (kt == qt && (tx * 4 + j) > (ty * 4 + i)) sv[i][j] = -1e10f;
            }

        // online softmax per row (reduce across 16 tx lanes, contiguous in warp)
#pragma unroll
        for (int i = 0; i < 4; i++) {
            float mx = fmaxf(fmaxf(sv[i][0], sv[i][1]), fmaxf(sv[i][2], sv[i][3]));
#pragma unroll
            for (int off = 8; off > 0; off >>= 1)
                mx = fmaxf(mx, __shfl_xor_sync(0xffffffffu, mx, off));
            float mnew = fmaxf(mrow[i], mx);
            float alpha = __expf(mrow[i] - mnew);
            float p0 = __expf(sv[i][0] - mnew);
            float p1 = __expf(sv[i][1] - mnew);
            float p2 = __expf(sv[i][2] - mnew);
            float p3 = __expf(sv[i][3] - mnew);
            float rs = p0 + p1 + p2 + p3;
#pragma unroll
            for (int off = 8; off > 0; off >>= 1)
                rs += __shfl_xor_sync(0xffffffffu, rs, off);
            lrow[i] = lrow[i] * alpha + rs;
            mrow[i] = mnew;
#pragma unroll
            for (int j = 0; j < 4; j++) o[i][j] *= alpha;
            float4 pw = make_float4(p0, p1, p2, p3);
            *reinterpret_cast<float4*>(Ps + (ty * 4 + i) * 68 + tx * 4) = pw;
        }
        __syncthreads();

        // O += P @ V
#pragma unroll 8
        for (int c = 0; c < 64; c++) {
            float4 vf = *reinterpret_cast<const float4*>(Vs + c * 64 + tx * 4);
#pragma unroll
            for (int i = 0; i < 4; i++) {
                float p = Ps[(ty * 4 + i) * 68 + c];
                o[i][0] = fmaf(p, vf.x, o[i][0]);
                o[i][1] = fmaf(p, vf.y, o[i][1]);
                o[i][2] = fmaf(p, vf.z, o[i][2]);
                o[i][3] = fmaf(p, vf.w, o[i][3]);
            }
        }
    }

    // epilogue: normalize and write to g_att[(b*S+s)][h*64+d]
    const int b = bh >> 4, h = bh & 15;
#pragma unroll
    for (int i = 0; i < 4; i++) {
        float inv = 1.f / lrow[i];
        int srow = qt * 64 + ty * 4 + i;
        float4 r;
        r.x = o[i][0] * inv; r.y = o[i][1] * inv;
        r.z = o[i][2] * inv; r.w = o[i][3] * inv;
        *reinterpret_cast<float4*>(g_att + (size_t)(b * SS + srow) * DD + h * 64 + tx * 4) = r;
    }
}

// ---------------------------------------------------------------------------
// Kernel 3: last-token top-8 tiles. Ranking tile-max logits is equivalent to
// ranking tile-max softmax probs (strictly monotone transform).
// One block per (b,h). Writes float(index) to d_out tail.
// ---------------------------------------------------------------------------
__global__ __launch_bounds__(256) void topk_kernel(float* __restrict__ out_idx)
{
    __shared__ float qsh[64];
    __shared__ float ls[2048];
    __shared__ float tile[128];
    const int bh = blockIdx.x;
    const int tid = threadIdx.x;
    const float* qrow = g_q + ((size_t)bh * SS + (SS - 1)) * HD;
    if (tid < 64) qsh[tid] = qrow[tid];
    __syncthreads();
    const float* kbase = g_k + (size_t)bh * SS * HD;
    for (int k = tid; k < SS; k += 256) {
        const float* kr = kbase + (size_t)k * HD;
        float acc = 0.f;
#pragma unroll
        for (int d = 0; d < 64; d++) acc = fmaf(qsh[d], kr[d], acc);
        ls[k] = acc;
    }
    __syncthreads();
    if (tid < 128) {
        float m = -INFINITY;
#pragma unroll
        for (int e = 0; e < 16; e++) m = fmaxf(m, ls[tid * 16 + e]);
        tile[tid] = m;
    }
    __syncthreads();
    if (tid == 0) {
        for (int slot = 0; slot < 8; slot++) {
            float best = -INFINITY; int bi = 0;
            for (int t = 0; t < 128; t++)
                if (tile[t] > best) { best = tile[t]; bi = t; }
            tile[bi] = -INFINITY;
            out_idx[bh * 8 + slot] = (float)bi;
        }
    }
}

// ---------------------------------------------------------------------------
// Kernel 4: output GEMM  out = g_att (4096x1024) @ wo (1024x1024)
// ---------------------------------------------------------------------------
__global__ __launch_bounds__(256) void out_gemm_kernel(
    const float* __restrict__ wo, float* __restrict__ out)
{
    __shared__ float As[8][132];
    __shared__ float Bs[8][128];
    const int n0 = blockIdx.x << 7;
    const int m0 = blockIdx.y << 7;
    const int tid = threadIdx.x;
    const int tx = tid & 15, ty = tid >> 4;

    float acc[8][8];
#pragma unroll
    for (int i = 0; i < 8; i++)
#pragma unroll
        for (int j = 0; j < 8; j++) acc[i][j] = 0.f;

    const int ar = tid >> 1, ac = (tid & 1) << 2;
    const int br = tid >> 5, bc = (tid & 31) << 2;

    for (int k0 = 0; k0 < DD; k0 += 8) {
        float4 av = *reinterpret_cast<const float4*>(g_att + (size_t)(m0 + ar) * DD + k0 + ac);
        float4 bv = *reinterpret_cast<const float4*>(wo + (size_t)(k0 + br) * DD + n0 + bc);
        As[ac + 0][ar] = av.x; As[ac + 1][ar] = av.y;
        As[ac + 2][ar] = av.z; As[ac + 3][ar] = av.w;
        *reinterpret_cast<float4*>(&Bs[br][bc]) = bv;
        __syncthreads();
#pragma unroll
        for (int kk = 0; kk < 8; kk++) {
            float a[8], b[8];
            float4 a0 = *reinterpret_cast<const float4*>(&As[kk][ty * 8]);
            float4 a1 = *reinterpret_cast<const float4*>(&As[kk][ty * 8 + 4]);
            a[0]=a0.x; a[1]=a0.y; a[2]=a0.z; a[3]=a0.w;
            a[4]=a1.x; a[5]=a1.y; a[6]=a1.z; a[7]=a1.w;
            float4 b0 = *reinterpret_cast<const float4*>(&Bs[kk][tx * 8]);
            float4 b1 = *reinterpret_cast<const float4*>(&Bs[kk][tx * 8 + 4]);
            b[0]=b0.x; b[1]=b0.y; b[2]=b0.z; b[3]=b0.w;
            b[4]=b1.x; b[5]=b1.y; b[6]=b1.z; b[7]=b1.w;
#pragma unroll
            for (int i = 0; i < 8; i++)
#pragma unroll
                for (int j = 0; j < 8; j++)
                    acc[i][j] = fmaf(a[i], b[j], acc[i][j]);
        }
        __syncthreads();
    }

#pragma unroll
    for (int i = 0; i < 8; i++) {
        const int m = m0 + ty * 8 + i;
        float4 r0 = make_float4(acc[i][0], acc[i][1], acc[i][2], acc[i][3]);
        float4 r1 = make_float4(acc[i][4], acc[i][5], acc[i][6], acc[i][7]);
        *reinterpret_cast<float4*>(out + (size_t)m * DD + n0 + tx * 8) = r0;
        *reinterpret_cast<float4*>(out + (size_t)m * DD + n0 + tx * 8 + 4) = r1;
    }
}

// ---------------------------------------------------------------------------
extern "C" void kernel_launch(void* const* d_in, const int* in_sizes, int n_in,
                              void* d_out, int out_size)
{
    const float* x  = (const float*)d_in[0];
    const float* wq = (const float*)d_in[1];
    const float* wk = (const float*)d_in[2];
    const float* wv = (const float*)d_in[3];
    const float* wo = (const float*)d_in[4];
    float* out = (float*)d_out;

    // QKV + RoPE
    qkv_gemm_kernel<<<dim3(24, 32), 256>>>(x, wq, wk, wv);

    // top-k tiles (depends only on g_q/g_k)
    topk_kernel<<<32, 256>>>(out + (size_t)MM * DD);

    // flash attention (dynamic smem: 3*64*68 + 64*64 floats)
    const int attn_smem = (3 * 64 * 68 + 64 * 64) * (int)sizeof(float);
    cudaFuncSetAttribute(attn_kernel, cudaFuncAttributeMaxDynamicSharedMemorySize, attn_smem);
    attn_kernel<<<dim3(32, 32), 256, attn_smem>>>();

    // output projection
    out_gemm_kernel<<<dim3(8, 32), 256>>>(wo, out);
}

// round 4
// speedup vs baseline: 1.4019x; 1.4019x over previous
#include <cuda_runtime.h>
#include <cuda_bf16.h>
#include <math.h>
#include <stdint.h>

#define BB 2
#define SS 2048
#define DD 1024
#define NH 16
#define HD 64
#define MM (BB*SS)

// ---------------------------------------------------------------------------
// Device scratch (allocation-free rule)
// ---------------------------------------------------------------------------
__device__ float g_q[(size_t)BB*NH*SS*HD];
__device__ float g_k[(size_t)BB*NH*SS*HD];
__device__ float g_v[(size_t)BB*NH*SS*HD];
__device__ __nv_bfloat16 g_xh[(size_t)MM*DD];
__device__ __nv_bfloat16 g_xl[(size_t)MM*DD];
__device__ __nv_bfloat16 g_wqkvt_h[(size_t)3*DD*DD];   // [3072 n][1024 k]
__device__ __nv_bfloat16 g_wqkvt_l[(size_t)3*DD*DD];
__device__ __nv_bfloat16 g_wot_h[(size_t)DD*DD];       // [1024 n][1024 k]
__device__ __nv_bfloat16 g_wot_l[(size_t)DD*DD];
__device__ __nv_bfloat16 g_atth[(size_t)MM*DD];
__device__ __nv_bfloat16 g_attl[(size_t)MM*DD];
__device__ float2 g_rope[(size_t)SS*32];               // cos,sin per (s, d/2)

// ---------------------------------------------------------------------------
// PTX helpers (base-ISA only: must compile for plain compute_103 / sm_103)
// ---------------------------------------------------------------------------
__device__ __forceinline__ uint32_t smem_u32(const void* p) {
    uint32_t a;
    asm("{ .reg .u64 t; cvta.to.shared.u64 t, %1; cvt.u32.u64 %0, t; }"
        : "=r"(a) : "l"(p));
    return a;
}
__device__ __forceinline__ void cp_async16(uint32_t dst, const void* src) {
    asm volatile("{\n .reg .u64 g;\n cvta.to.global.u64 g, %1;\n"
                 " cp.async.cg.shared.global [%0], [g], 16;\n}"
                 :: "r"(dst), "l"(src) : "memory");
}
#define CP_COMMIT() asm volatile("cp.async.commit_group;" ::: "memory")
template <int N>
__device__ __forceinline__ void cp_wait() {
    asm volatile("cp.async.wait_group %0;" :: "n"(N) : "memory");
}
__device__ __forceinline__ void ldmatrix_x4(uint32_t* r, uint32_t addr) {
    asm volatile("ldmatrix.sync.aligned.m8n8.x4.shared.b16 {%0,%1,%2,%3}, [%4];"
                 : "=r"(r[0]), "=r"(r[1]), "=r"(r[2]), "=r"(r[3]) : "r"(addr));
}
__device__ __forceinline__ void mma_bf16(float* d, const uint32_t* a, const uint32_t* b) {
    asm volatile(
        "mma.sync.aligned.m16n8k16.row.col.f32.bf16.bf16.f32 "
        "{%0,%1,%2,%3}, {%4,%5,%6,%7}, {%8,%9}, {%0,%1,%2,%3};"
        : "+f"(d[0]), "+f"(d[1]), "+f"(d[2]), "+f"(d[3])
        : "r"(a[0]), "r"(a[1]), "r"(a[2]), "r"(a[3]), "r"(b[0]), "r"(b[1]));
}

// ---------------------------------------------------------------------------
// Prep kernel A: x -> bf16 hi/lo
// ---------------------------------------------------------------------------
__global__ __launch_bounds__(256) void convert_x_kernel(const float* __restrict__ x)
{
    size_t idx = (size_t)blockIdx.x * 256 + threadIdx.x;   // one float4
    float4 v = reinterpret_cast<const float4*>(x)[idx];
    __nv_bfloat16 h0 = __float2bfloat16(v.x), h1 = __float2bfloat16(v.y);
    __nv_bfloat16 h2 = __float2bfloat16(v.z), h3 = __float2bfloat16(v.w);
    __nv_bfloat162 hv0; hv0.x = h0; hv0.y = h1;
    __nv_bfloat162 hv1; hv1.x = h2; hv1.y = h3;
    __nv_bfloat162 lv0, lv1;
    lv0.x = __float2bfloat16(v.x - __bfloat162float(h0));
    lv0.y = __float2bfloat16(v.y - __bfloat162float(h1));
    lv1.x = __float2bfloat16(v.z - __bfloat162float(h2));
    lv1.y = __float2bfloat16(v.w - __bfloat162float(h3));
    reinterpret_cast<__nv_bfloat162*>(g_xh)[idx * 2 + 0] = hv0;
    reinterpret_cast<__nv_bfloat162*>(g_xh)[idx * 2 + 1] = hv1;
    reinterpret_cast<__nv_bfloat162*>(g_xl)[idx * 2 + 0] = lv0;
    reinterpret_cast<__nv_bfloat162*>(g_xl)[idx * 2 + 1] = lv1;
}

// ---------------------------------------------------------------------------
// Prep kernel B: transpose weights -> N-major bf16 hi/lo
// ---------------------------------------------------------------------------
__global__ __launch_bounds__(256) void transpose_w_kernel(
    const float* __restrict__ wq, const float* __restrict__ wk,
    const float* __restrict__ wv, const float* __restrict__ wo)
{
    __shared__ float tile[32][33];
    const int mat = blockIdx.z;
    const float* src = (mat == 0) ? wq : (mat == 1) ? wk : (mat == 2) ? wv : wo;
    const int k0 = blockIdx.y * 32, n0 = blockIdx.x * 32;
    const int tx = threadIdx.x, ty = threadIdx.y;     // 32 x 8
#pragma unroll
    for (int i = 0; i < 32; i += 8)
        tile[ty + i][tx] = src[(size_t)(k0 + ty + i) * DD + n0 + tx];
    __syncthreads();
    __nv_bfloat16* dh;
    __nv_bfloat16* dl;
    size_t rowoff;
    if (mat < 3) { dh = g_wqkvt_h; dl = g_wqkvt_l; rowoff = (size_t)mat * DD; }
    else         { dh = g_wot_h;   dl = g_wot_l;   rowoff = 0; }
#pragma unroll
    for (int i = 0; i < 32; i += 8) {
        float v = tile[tx][ty + i];                   // = w[k0+tx][n0+ty+i]
        __nv_bfloat16 h = __float2bfloat16(v);
        __nv_bfloat16 l = __float2bfloat16(v - __bfloat162float(h));
        size_t di = (rowoff + n0 + ty + i) * DD + k0 + tx;
        dh[di] = h;
        dl[di] = l;
    }
}

// ---------------------------------------------------------------------------
// Prep kernel C: RoPE cos/sin table
// ---------------------------------------------------------------------------
__global__ void rope_table_kernel()
{
    int s = blockIdx.x;
    int dp = threadIdx.x;    // 0..31, pair index
    float inv = expf(-0.14391156831212807f * (float)(2 * dp));
    float ang = (float)s * inv;
    float sn, cs;
    sincosf(ang, &sn, &cs);
    g_rope[s * 32 + dp] = make_float2(cs, sn);
}

// ---------------------------------------------------------------------------
// HMMA GEMM: C[128,128] tile of A[M,1024] @ B^T (B stored [N,1024] K-major)
// Split precision: D = Ah*Bh + Ah*Bl + Al*Bh, fp32 accum in registers.
// Operand pointers selected IN DEVICE CODE from `mode` (host cannot pass
// __device__ symbols — on GB300/ATS the bogus host pointer reads as zeros).
// mode 0: A=g_xh/g_xl, B=g_wqkvt (+RoPE epilogue -> g_q/g_k/g_v)
// mode 1: A=g_atth/g_attl, B=g_wot (store fp32 to outp)
// ---------------------------------------------------------------------------
#define ROWB 80                     // smem row stride bytes (40 bf16)
#define MATB (128 * ROWB)           // 10240 bytes per matrix tile
#define STGB (4 * MATB)             // 40960 per stage
#define GEMM_SMEM_BYTES (2 * STGB)  // 81920

__global__ __launch_bounds__(256, 1) void mma_gemm_kernel(
    int mode, float* __restrict__ outp)
{
    extern __shared__ char sm[];
    const uint32_t sb = smem_u32(sm);
    const int tid = threadIdx.x, wid = tid >> 5, lid = tid & 31;
    const int m0 = blockIdx.y << 7, n0 = blockIdx.x << 7;
    const int wm = wid & 1, wn = wid >> 1;

    const __nv_bfloat16* __restrict__ Ah = (mode == 0) ? g_xh : g_atth;
    const __nv_bfloat16* __restrict__ Al = (mode == 0) ? g_xl : g_attl;
    const __nv_bfloat16* __restrict__ Bh = (mode == 0) ? g_wqkvt_h : g_wot_h;
    const __nv_bfloat16* __restrict__ Bl = (mode == 0) ? g_wqkvt_l : g_wot_l;

    float acc[4][4][4];
#pragma unroll
    for (int i = 0; i < 4; i++)
#pragma unroll
        for (int j = 0; j < 4; j++)
#pragma unroll
            for (int r = 0; r < 4; r++) acc[i][j][r] = 0.f;

    // per-thread gmem->smem assignment: 8 chunks of 16B
    const int ld_r = tid >> 2;            // 0..63 base row (x2)
    const int ld_c = tid & 3;             // 16B column within 64B row

    auto issue_stage = [&](int t, int stg) {
        const int k0 = t << 5;
        const uint32_t dst0 = sb + (uint32_t)stg * STGB;
#pragma unroll
        for (int q = 0; q < 4; q++) {
            const __nv_bfloat16* S = (q == 0) ? Ah : (q == 1) ? Al : (q == 2) ? Bh : Bl;
            const int rbase = (q < 2) ? m0 : n0;
#pragma unroll
            for (int half = 0; half < 2; half++) {
                int r = ld_r + half * 64;
                cp_async16(dst0 + q * MATB + r * ROWB + ld_c * 16,
                           S + (size_t)(rbase + r) * DD + k0 + ld_c * 8);
            }
        }
    };

    issue_stage(0, 0);
    CP_COMMIT();

    for (int t = 0; t < 32; t++) {
        if (t + 1 < 32) {
            issue_stage(t + 1, (t + 1) & 1);
            CP_COMMIT();
            cp_wait<1>();
        } else {
            cp_wait<0>();
        }
        __syncthreads();

        const uint32_t stg = sb + (uint32_t)(t & 1) * STGB;
        const uint32_t sAh = stg, sAl = stg + MATB;
        const uint32_t sBh = stg + 2 * MATB, sBl = stg + 3 * MATB;

#pragma unroll
        for (int ks = 0; ks < 2; ks++) {
            uint32_t ah[4][4], al[4][4], bh[4][2], bl[4][2];
            const uint32_t akb = ks * 32 + ((lid & 16) ? 16 : 0);
            const uint32_t arow = wm * 64 + (lid & 15);
#pragma unroll
            for (int mt = 0; mt < 4; mt++) {
                ldmatrix_x4(ah[mt], sAh + (arow + mt * 16) * ROWB + akb);
                ldmatrix_x4(al[mt], sAl + (arow + mt * 16) * ROWB + akb);
            }
            const uint32_t bg = lid >> 3, brl = lid & 7;
            const uint32_t bkb = ks * 32 + ((bg & 1) ? 16 : 0);
#pragma unroll
            for (int p = 0; p < 2; p++) {
                uint32_t nrow = wn * 32 + p * 16 + ((bg & 2) ? 8 : 0) + brl;
                uint32_t tmp[4];
                ldmatrix_x4(tmp, sBh + nrow * ROWB + bkb);
                bh[2 * p][0] = tmp[0]; bh[2 * p][1] = tmp[1];
                bh[2 * p + 1][0] = tmp[2]; bh[2 * p + 1][1] = tmp[3];
                ldmatrix_x4(tmp, sBl + nrow * ROWB + bkb);
                bl[2 * p][0] = tmp[0]; bl[2 * p][1] = tmp[1];
                bl[2 * p + 1][0] = tmp[2]; bl[2 * p + 1][1] = tmp[3];
            }
#pragma unroll
            for (int mt = 0; mt < 4; mt++)
#pragma unroll
                for (int nt = 0; nt < 4; nt++) {
                    mma_bf16(acc[mt][nt], ah[mt], bh[nt]);
                    mma_bf16(acc[mt][nt], al[mt], bh[nt]);
                    mma_bf16(acc[mt][nt], ah[mt], bl[nt]);
                }
        }
        __syncthreads();
    }

    // Epilogue from registers
#pragma unroll
    for (int mt = 0; mt < 4; mt++) {
#pragma unroll
        for (int nt = 0; nt < 4; nt++) {
            const int row = m0 + wm * 64 + mt * 16 + (lid >> 2);
            const int col = n0 + wn * 32 + nt * 8 + ((lid & 3) << 1);
#pragma unroll
            for (int half = 0; half < 2; half++) {
                const int r = row + half * 8;
                float v0 = acc[mt][nt][half * 2 + 0];
                float v1 = acc[mt][nt][half * 2 + 1];
                if (mode == 0) {
                    const int which = col >> 10;
                    const int nn = col & 1023;
                    const int h = nn >> 6, d = nn & 63;
                    const int b = r >> 11, s = r & 2047;
                    if (which < 2) {
                        float2 cs = g_rope[s * 32 + (d >> 1)];
                        float r0 = v0 * cs.x - v1 * cs.y;
                        float r1 = v0 * cs.y + v1 * cs.x;
                        v0 = r0; v1 = r1;
                    }
                    float* dst = (which == 0) ? g_q : (which == 1) ? g_k : g_v;
                    *reinterpret_cast<float2*>(
                        dst + (((size_t)(b * NH + h)) * SS + s) * HD + d) =
                        make_float2(v0, v1);
                } else {
                    *reinterpret_cast<float2*>(outp + (size_t)r * DD + col) =
                        make_float2(v0, v1);
                }
            }
        }
    }
}

// ---------------------------------------------------------------------------
// Causal flash attention, fp32 SIMT; writes bf16 hi/lo att for out-proj GEMM.
// ---------------------------------------------------------------------------
__global__ __launch_bounds__(256) void attn_kernel()
{
    extern __shared__ float smf[];
    float* Qs = smf;                // [64][68] Qs[d][m]
    float* Ks = Qs + 64 * 68;       // [64][68] Ks[d][c]
    float* Ps = Ks + 64 * 68;       // [64][68]
    float* Vs = Ps + 64 * 68;       // [64][64]

    const int qt = blockIdx.x;
    const int bh = blockIdx.y;
    const int tid = threadIdx.x;
    const int tx = tid & 15, ty = tid >> 4;
    const float* qp = g_q + (size_t)bh * SS * HD;
    const float* kp = g_k + (size_t)bh * SS * HD;
    const float* vp = g_v + (size_t)bh * SS * HD;

    for (int it = tid; it < 1024; it += 256) {
        int r = it >> 4, c4 = (it & 15) << 2;
        float4 v = *reinterpret_cast<const float4*>(qp + (size_t)(qt * 64 + r) * HD + c4);
        Qs[(c4 + 0) * 68 + r] = v.x; Qs[(c4 + 1) * 68 + r] = v.y;
        Qs[(c4 + 2) * 68 + r] = v.z; Qs[(c4 + 3) * 68 + r] = v.w;
    }

    float o[4][4];
    float mrow[4], lrow[4];
#pragma unroll
    for (int i = 0; i < 4; i++) {
        mrow[i] = -INFINITY; lrow[i] = 0.f;
#pragma unroll
        for (int j = 0; j < 4; j++) o[i][j] = 0.f;
    }

    for (int kt = 0; kt <= qt; kt++) {
        __syncthreads();
        for (int it = tid; it < 1024; it += 256) {
            int r = it >> 4, c4 = (it & 15) << 2;
            float4 kv = *reinterpret_cast<const float4*>(kp + (size_t)(kt * 64 + r) * HD + c4);
            Ks[(c4 + 0) * 68 + r] = kv.x; Ks[(c4 + 1) * 68 + r] = kv.y;
            Ks[(c4 + 2) * 68 + r] = kv.z; Ks[(c4 + 3) * 68 + r] = kv.w;
            float4 vv = *reinterpret_cast<const float4*>(vp + (size_t)(kt * 64 + r) * HD + c4);
            *reinterpret_cast<float4*>(&Vs[r * 64 + c4]) = vv;
        }
        __syncthreads();

        float sv[4][4];
#pragma unroll
        for (int i = 0; i < 4; i++)
#pragma unroll
            for (int j = 0; j < 4; j++) sv[i][j] = 0.f;
#pragma unroll 8
        for (int kk = 0; kk < 64; kk++) {
            float4 a = *reinterpret_cast<const float4*>(Qs + kk * 68 + ty * 4);
            float4 bq = *reinterpret_cast<const float4*>(Ks + kk * 68 + tx * 4);
            float af[4] = {a.x, a.y, a.z, a.w};
            float bf[4] = {bq.x, bq.y, bq.z, bq.w};
#pragma unroll
            for (int i = 0; i < 4; i++)
#pragma unroll
                for (int j = 0; j < 4; j++)
                    sv[i][j] = fmaf(af[i], bf[j], sv[i][j]);
        }
#pragma unroll
        for (int i = 0; i < 4; i++)
#pragma unroll
            for (int j = 0; j < 4; j++) {
                sv[i][j] *= 0.125f;
                if (kt == qt && (tx * 4 + j) > (ty * 4 + i)) sv[i][j] = -1e10f;
            }

#pragma unroll
        for (int i = 0; i < 4; i++) {
            float mx = fmaxf(fmaxf(sv[i][0], sv[i][1]), fmaxf(sv[i][2], sv[i][3]));
#pragma unroll
            for (int off = 8; off > 0; off >>= 1)
                mx = fmaxf(mx, __shfl_xor_sync(0xffffffffu, mx, off));
            float mnew = fmaxf(mrow[i], mx);
            float alpha = __expf(mrow[i] - mnew);
            float p0 = __expf(sv[i][0] - mnew);
            float p1 = __expf(sv[i][1] - mnew);
            float p2 = __expf(sv[i][2] - mnew);
            float p3 = __expf(sv[i][3] - mnew);
            float rs = p0 + p1 + p2 + p3;
#pragma unroll
            for (int off = 8; off > 0; off >>= 1)
                rs += __shfl_xor_sync(0xffffffffu, rs, off);
            lrow[i] = lrow[i] * alpha + rs;
            mrow[i] = mnew;
#pragma unroll
            for (int j = 0; j < 4; j++) o[i][j] *= alpha;
            *reinterpret_cast<float4*>(Ps + (ty * 4 + i) * 68 + tx * 4) =
                make_float4(p0, p1, p2, p3);
        }
        __syncthreads();

#pragma unroll 8
        for (int c = 0; c < 64; c++) {
            float4 vf = *reinterpret_cast<const float4*>(Vs + c * 64 + tx * 4);
#pragma unroll
            for (int i = 0; i < 4; i++) {
                float p = Ps[(ty * 4 + i) * 68 + c];
                o[i][0] = fmaf(p, vf.x, o[i][0]);
                o[i][1] = fmaf(p, vf.y, o[i][1]);
                o[i][2] = fmaf(p, vf.z, o[i][2]);
                o[i][3] = fmaf(p, vf.w, o[i][3]);
            }
        }
    }

    const int b = bh >> 4, h = bh & 15;
#pragma unroll
    for (int i = 0; i < 4; i++) {
        float inv = 1.f / lrow[i];
        int srow = qt * 64 + ty * 4 + i;
        size_t base = ((size_t)(b * SS + srow)) * DD + h * 64 + tx * 4;
        float v0 = o[i][0] * inv, v1 = o[i][1] * inv;
        float v2 = o[i][2] * inv, v3 = o[i][3] * inv;
        __nv_bfloat16 h0 = __float2bfloat16(v0), h1 = __float2bfloat16(v1);
        __nv_bfloat16 h2 = __float2bfloat16(v2), h3 = __float2bfloat16(v3);
        __nv_bfloat162 hh0; hh0.x = h0; hh0.y = h1;
        __nv_bfloat162 hh1; hh1.x = h2; hh1.y = h3;
        __nv_bfloat162 ll0; ll0.x = __float2bfloat16(v0 - __bfloat162float(h0));
        ll0.y = __float2bfloat16(v1 - __bfloat162float(h1));
        __nv_bfloat162 ll1; ll1.x = __float2bfloat16(v2 - __bfloat162float(h2));
        ll1.y = __float2bfloat16(v3 - __bfloat162float(h3));
        *reinterpret_cast<__nv_bfloat162*>(g_atth + base) = hh0;
        *reinterpret_cast<__nv_bfloat162*>(g_atth + base + 2) = hh1;
        *reinterpret_cast<__nv_bfloat162*>(g_attl + base) = ll0;
        *reinterpret_cast<__nv_bfloat162*>(g_attl + base + 2) = ll1;
    }
}

// ---------------------------------------------------------------------------
// Top-8 tiles from last token (rank by tile-max logits — monotone w/ softmax)
// ---------------------------------------------------------------------------
__global__ __launch_bounds__(256) void topk_kernel(float* __restrict__ out_idx)
{
    __shared__ float qsh[64];
    __shared__ float ls[2048];
    __shared__ float tile[128];
    const int bh = blockIdx.x;
    const int tid = threadIdx.x;
    const float* qrow = g_q + ((size_t)bh * SS + (SS - 1)) * HD;
    if (tid < 64) qsh[tid] = qrow[tid];
    __syncthreads();
    const float* kbase = g_k + (size_t)bh * SS * HD;
    for (int k = tid; k < SS; k += 256) {
        const float* kr = kbase + (size_t)k * HD;
        float acc = 0.f;
#pragma unroll
        for (int d = 0; d < 64; d++) acc = fmaf(qsh[d], kr[d], acc);
        ls[k] = acc;
    }
    __syncthreads();
    if (tid < 128) {
        float m = -INFINITY;
#pragma unroll
        for (int e = 0; e < 16; e++) m = fmaxf(m, ls[tid * 16 + e]);
        tile[tid] = m;
    }
    __syncthreads();
    if (tid == 0) {
        for (int slot = 0; slot < 8; slot++) {
            float best = -INFINITY; int bi = 0;
            for (int t = 0; t < 128; t++)
                if (tile[t] > best) { best = tile[t]; bi = t; }
            tile[bi] = -INFINITY;
            out_idx[bh * 8 + slot] = (float)bi;
        }
    }
}

// ---------------------------------------------------------------------------
extern "C" void kernel_launch(void* const* d_in, const int* in_sizes, int n_in,
                              void* d_out, int out_size)
{
    const float* x  = (const float*)d_in[0];
    const float* wq = (const float*)d_in[1];
    const float* wk = (const float*)d_in[2];
    const float* wv = (const float*)d_in[3];
    const float* wo = (const float*)d_in[4];
    float* out = (float*)d_out;

    cudaFuncSetAttribute(mma_gemm_kernel,
                         cudaFuncAttributeMaxDynamicSharedMemorySize, GEMM_SMEM_BYTES);
    const int attn_smem = (3 * 64 * 68 + 64 * 64) * (int)sizeof(float);
    cudaFuncSetAttribute(attn_kernel,
                         cudaFuncAttributeMaxDynamicSharedMemorySize, attn_smem);

    // prep
    convert_x_kernel<<<(MM * DD) / 4 / 256, 256>>>(x);
    transpose_w_kernel<<<dim3(32, 32, 4), dim3(32, 8)>>>(wq, wk, wv, wo);
    rope_table_kernel<<<SS, 32>>>();

    // QKV GEMM + RoPE (HMMA)
    mma_gemm_kernel<<<dim3(24, 32), 256, GEMM_SMEM_BYTES>>>(0, nullptr);

    // top-k tiles
    topk_kernel<<<32, 256>>>(out + (size_t)MM * DD);

    // attention
    attn_kernel<<<dim3(32, 32), 256, attn_smem>>>();

    // output projection (HMMA)
    mma_gemm_kernel<<<dim3(8, 32), 256, GEMM_SMEM_BYTES>>>(1, out);
}

// round 6
// speedup vs baseline: 2.3590x; 1.6827x over previous
#include <cuda_runtime.h>
#include <cuda_bf16.h>
#include <math.h>
#include <stdint.h>

#define BB 2
#define SS 2048
#define DD 1024
#define NH 16
#define HD 64
#define MM (BB*SS)

// ---------------------------------------------------------------------------
// Device scratch (allocation-free rule). All referenced ONLY from device code.
// ---------------------------------------------------------------------------
__device__ __nv_bfloat16 g_xh[(size_t)MM*DD];
__device__ __nv_bfloat16 g_xl[(size_t)MM*DD];
__device__ __nv_bfloat16 g_wqkvt_h[(size_t)3*DD*DD];   // [3072 n][1024 k]
__device__ __nv_bfloat16 g_wqkvt_l[(size_t)3*DD*DD];
__device__ __nv_bfloat16 g_wot_h[(size_t)DD*DD];       // [1024 n][1024 k]
__device__ __nv_bfloat16 g_wot_l[(size_t)DD*DD];
__device__ __nv_bfloat16 g_qh[(size_t)BB*NH*SS*HD];    // [bh][s][d]
__device__ __nv_bfloat16 g_ql[(size_t)BB*NH*SS*HD];
__device__ __nv_bfloat16 g_kh[(size_t)BB*NH*SS*HD];
__device__ __nv_bfloat16 g_kl[(size_t)BB*NH*SS*HD];
__device__ __nv_bfloat16 g_vth[(size_t)BB*NH*HD*SS];   // [bh][d][s] transposed
__device__ __nv_bfloat16 g_vtl[(size_t)BB*NH*HD*SS];
__device__ __nv_bfloat16 g_atth[(size_t)MM*DD];
__device__ __nv_bfloat16 g_attl[(size_t)MM*DD];
__device__ float2 g_rope[(size_t)SS*32];               // cos,sin per (s, d/2)

// ---------------------------------------------------------------------------
// PTX helpers (base ISA only — must compile for plain compute_103)
// ---------------------------------------------------------------------------
__device__ __forceinline__ uint32_t smem_u32(const void* p) {
    uint32_t a;
    asm("{ .reg .u64 t; cvta.to.shared.u64 t, %1; cvt.u32.u64 %0, t; }"
        : "=r"(a) : "l"(p));
    return a;
}
__device__ __forceinline__ void cp_async16(uint32_t dst, const void* src) {
    asm volatile("{\n .reg .u64 g;\n cvta.to.global.u64 g, %1;\n"
                 " cp.async.cg.shared.global [%0], [g], 16;\n}"
                 :: "r"(dst), "l"(src) : "memory");
}
#define CP_COMMIT() asm volatile("cp.async.commit_group;" ::: "memory")
template <int N>
__device__ __forceinline__ void cp_wait() {
    asm volatile("cp.async.wait_group %0;" :: "n"(N) : "memory");
}
__device__ __forceinline__ void ldmatrix_x4(uint32_t* r, uint32_t addr) {
    asm volatile("ldmatrix.sync.aligned.m8n8.x4.shared.b16 {%0,%1,%2,%3}, [%4];"
                 : "=r"(r[0]), "=r"(r[1]), "=r"(r[2]), "=r"(r[3]) : "r"(addr));
}
__device__ __forceinline__ void mma_bf16(float* d, const uint32_t* a, const uint32_t* b) {
    asm volatile(
        "mma.sync.aligned.m16n8k16.row.col.f32.bf16.bf16.f32 "
        "{%0,%1,%2,%3}, {%4,%5,%6,%7}, {%8,%9}, {%0,%1,%2,%3};"
        : "+f"(d[0]), "+f"(d[1]), "+f"(d[2]), "+f"(d[3])
        : "r"(a[0]), "r"(a[1]), "r"(a[2]), "r"(a[3]), "r"(b[0]), "r"(b[1]));
}
// pack two fp32 -> bf16x2 hi + residual-lo words
__device__ __forceinline__ void split2(float a, float b, uint32_t& hi, uint32_t& lo) {
    __nv_bfloat16 ah = __float2bfloat16(a), bh = __float2bfloat16(b);
    __nv_bfloat162 h; h.x = ah; h.y = bh;
    __nv_bfloat162 l;
    l.x = __float2bfloat16(a - __bfloat162float(ah));
    l.y = __float2bfloat16(b - __bfloat162float(bh));
    hi = *reinterpret_cast<uint32_t*>(&h);
    lo = *reinterpret_cast<uint32_t*>(&l);
}

// ---------------------------------------------------------------------------
// Prep kernel A: x -> bf16 hi/lo
// ---------------------------------------------------------------------------
__global__ __launch_bounds__(256) void convert_x_kernel(const float* __restrict__ x)
{
    size_t idx = (size_t)blockIdx.x * 256 + threadIdx.x;   // one float4
    float4 v = reinterpret_cast<const float4*>(x)[idx];
    uint32_t h0, l0, h1, l1;
    split2(v.x, v.y, h0, l0);
    split2(v.z, v.w, h1, l1);
    reinterpret_cast<uint32_t*>(g_xh)[idx * 2 + 0] = h0;
    reinterpret_cast<uint32_t*>(g_xh)[idx * 2 + 1] = h1;
    reinterpret_cast<uint32_t*>(g_xl)[idx * 2 + 0] = l0;
    reinterpret_cast<uint32_t*>(g_xl)[idx * 2 + 1] = l1;
}

// ---------------------------------------------------------------------------
// Prep kernel B: transpose weights -> N-major bf16 hi/lo
// ---------------------------------------------------------------------------
__global__ __launch_bounds__(256) void transpose_w_kernel(
    const float* __restrict__ wq, const float* __restrict__ wk,
    const float* __restrict__ wv, const float* __restrict__ wo)
{
    __shared__ float tile[32][33];
    const int mat = blockIdx.z;
    const float* src = (mat == 0) ? wq : (mat == 1) ? wk : (mat == 2) ? wv : wo;
    const int k0 = blockIdx.y * 32, n0 = blockIdx.x * 32;
    const int tx = threadIdx.x, ty = threadIdx.y;     // 32 x 8
#pragma unroll
    for (int i = 0; i < 32; i += 8)
        tile[ty + i][tx] = src[(size_t)(k0 + ty + i) * DD + n0 + tx];
    __syncthreads();
    __nv_bfloat16* dh;
    __nv_bfloat16* dl;
    size_t rowoff;
    if (mat < 3) { dh = g_wqkvt_h; dl = g_wqkvt_l; rowoff = (size_t)mat * DD; }
    else         { dh = g_wot_h;   dl = g_wot_l;   rowoff = 0; }
#pragma unroll
    for (int i = 0; i < 32; i += 8) {
        float v = tile[tx][ty + i];                   // = w[k0+tx][n0+ty+i]
        __nv_bfloat16 h = __float2bfloat16(v);
        __nv_bfloat16 l = __float2bfloat16(v - __bfloat162float(h));
        size_t di = (rowoff + n0 + ty + i) * DD + k0 + tx;
        dh[di] = h;
        dl[di] = l;
    }
}

// ---------------------------------------------------------------------------
// Prep kernel C: RoPE cos/sin table
// ---------------------------------------------------------------------------
__global__ void rope_table_kernel()
{
    int s = blockIdx.x;
    int dp = threadIdx.x;    // 0..31, pair index
    float inv = expf(-0.14391156831212807f * (float)(2 * dp));
    float ang = (float)s * inv;
    float sn, cs;
    sincosf(ang, &sn, &cs);
    g_rope[s * 32 + dp] = make_float2(cs, sn);
}

// ---------------------------------------------------------------------------
// HMMA GEMM (split bf16): mode 0 = QKV+RoPE, mode 1 = out-proj.
// ---------------------------------------------------------------------------
#define ROWB 80                     // smem row stride bytes (rows hold 32 bf16)
#define MATB (128 * ROWB)           // 10240 bytes per matrix tile
#define STGB (4 * MATB)             // 40960 per stage
#define GEMM_SMEM_BYTES (2 * STGB)  // 81920

__global__ __launch_bounds__(256, 1) void mma_gemm_kernel(
    int mode, float* __restrict__ outp)
{
    extern __shared__ char sm[];
    const uint32_t sb = smem_u32(sm);
    const int tid = threadIdx.x, wid = tid >> 5, lid = tid & 31;
    const int m0 = blockIdx.y << 7, n0 = blockIdx.x << 7;
    const int wm = wid & 1, wn = wid >> 1;

    const __nv_bfloat16* __restrict__ Ah = (mode == 0) ? g_xh : g_atth;
    const __nv_bfloat16* __restrict__ Al = (mode == 0) ? g_xl : g_attl;
    const __nv_bfloat16* __restrict__ Bh = (mode == 0) ? g_wqkvt_h : g_wot_h;
    const __nv_bfloat16* __restrict__ Bl = (mode == 0) ? g_wqkvt_l : g_wot_l;

    float acc[4][4][4];
#pragma unroll
    for (int i = 0; i < 4; i++)
#pragma unroll
        for (int j = 0; j < 4; j++)
#pragma unroll
            for (int r = 0; r < 4; r++) acc[i][j][r] = 0.f;

    const int ld_r = tid >> 2;
    const int ld_c = tid & 3;

    auto issue_stage = [&](int t, int stg) {
        const int k0 = t << 5;
        const uint32_t dst0 = sb + (uint32_t)stg * STGB;
#pragma unroll
        for (int q = 0; q < 4; q++) {
            const __nv_bfloat16* S = (q == 0) ? Ah : (q == 1) ? Al : (q == 2) ? Bh : Bl;
            const int rbase = (q < 2) ? m0 : n0;
#pragma unroll
            for (int half = 0; half < 2; half++) {
                int r = ld_r + half * 64;
                cp_async16(dst0 + q * MATB + r * ROWB + ld_c * 16,
                           S + (size_t)(rbase + r) * DD + k0 + ld_c * 8);
            }
        }
    };

    issue_stage(0, 0);
    CP_COMMIT();

    for (int t = 0; t < 32; t++) {
        if (t + 1 < 32) {
            issue_stage(t + 1, (t + 1) & 1);
            CP_COMMIT();
            cp_wait<1>();
        } else {
            cp_wait<0>();
        }
        __syncthreads();

        const uint32_t stg = sb + (uint32_t)(t & 1) * STGB;
        const uint32_t sAh = stg, sAl = stg + MATB;
        const uint32_t sBh = stg + 2 * MATB, sBl = stg + 3 * MATB;

#pragma unroll
        for (int ks = 0; ks < 2; ks++) {
            uint32_t ah[4][4], al[4][4], bh[4][2], bl[4][2];
            const uint32_t akb = ks * 32 + ((lid & 16) ? 16 : 0);
            const uint32_t arow = wm * 64 + (lid & 15);
#pragma unroll
            for (int mt = 0; mt < 4; mt++) {
                ldmatrix_x4(ah[mt], sAh + (arow + mt * 16) * ROWB + akb);
                ldmatrix_x4(al[mt], sAl + (arow + mt * 16) * ROWB + akb);
            }
            const uint32_t bg = lid >> 3, brl = lid & 7;
            const uint32_t bkb = ks * 32 + ((bg & 1) ? 16 : 0);
#pragma unroll
            for (int p = 0; p < 2; p++) {
                uint32_t nrow = wn * 32 + p * 16 + ((bg & 2) ? 8 : 0) + brl;
                uint32_t tmp[4];
                ldmatrix_x4(tmp, sBh + nrow * ROWB + bkb);
                bh[2 * p][0] = tmp[0]; bh[2 * p][1] = tmp[1];
                bh[2 * p + 1][0] = tmp[2]; bh[2 * p + 1][1] = tmp[3];
                ldmatrix_x4(tmp, sBl + nrow * ROWB + bkb);
                bl[2 * p][0] = tmp[0]; bl[2 * p][1] = tmp[1];
                bl[2 * p + 1][0] = tmp[2]; bl[2 * p + 1][1] = tmp[3];
            }
#pragma unroll
            for (int mt = 0; mt < 4; mt++)
#pragma unroll
                for (int nt = 0; nt < 4; nt++) {
                    mma_bf16(acc[mt][nt], ah[mt], bh[nt]);
                    mma_bf16(acc[mt][nt], al[mt], bh[nt]);
                    mma_bf16(acc[mt][nt], ah[mt], bl[nt]);
                }
        }
        __syncthreads();
    }

    // Epilogue
#pragma unroll
    for (int mt = 0; mt < 4; mt++) {
#pragma unroll
        for (int nt = 0; nt < 4; nt++) {
            const int row = m0 + wm * 64 + mt * 16 + (lid >> 2);
            const int col = n0 + wn * 32 + nt * 8 + ((lid & 3) << 1);
#pragma unroll
            for (int half = 0; half < 2; half++) {
                const int r = row + half * 8;
                float v0 = acc[mt][nt][half * 2 + 0];
                float v1 = acc[mt][nt][half * 2 + 1];
                if (mode == 0) {
                    const int which = col >> 10;
                    const int nn = col & 1023;
                    const int h = nn >> 6, d = nn & 63;
                    const int b = r >> 11, s = r & 2047;
                    const size_t bh = (size_t)(b * NH + h);
                    if (which < 2) {
                        float2 cs = g_rope[s * 32 + (d >> 1)];
                        float r0 = v0 * cs.x - v1 * cs.y;
                        float r1 = v0 * cs.y + v1 * cs.x;
                        v0 = r0; v1 = r1;
                        uint32_t hi, lo;
                        split2(v0, v1, hi, lo);
                        size_t base = (bh * SS + s) * HD + d;
                        __nv_bfloat16* dh = (which == 0) ? g_qh : g_kh;
                        __nv_bfloat16* dl = (which == 0) ? g_ql : g_kl;
                        *reinterpret_cast<uint32_t*>(dh + base) = hi;
                        *reinterpret_cast<uint32_t*>(dl + base) = lo;
                    } else {
                        // V: transposed bf16 hi/lo [bh][d][s]
                        __nv_bfloat16 h0 = __float2bfloat16(v0);
                        __nv_bfloat16 h1 = __float2bfloat16(v1);
                        size_t vb = (bh * HD + d) * SS + s;
                        g_vth[vb] = h0;
                        g_vth[vb + SS] = h1;
                        g_vtl[vb] = __float2bfloat16(v0 - __bfloat162float(h0));
                        g_vtl[vb + SS] = __float2bfloat16(v1 - __bfloat162float(h1));
                    }
                } else {
                    *reinterpret_cast<float2*>(outp + (size_t)r * DD + col) =
                        make_float2(v0, v1);
                }
            }
        }
    }
}

// ---------------------------------------------------------------------------
// HMMA flash attention. CTA = 128 q rows x (b,h). 8 warps (warp = m16).
// KV tiles of 64, cp.async double-buffered. Split-bf16 for QK^T and PV.
// Rows hold HD=64 bf16 = 128 bytes -> row stride 144 bytes (pad 16).
// ---------------------------------------------------------------------------
#define AT_ROWB 144
#define AT_QB (128 * AT_ROWB)                 // 18432 per Q matrix
#define AT_KVB (64 * AT_ROWB)                 // 9216 per KV matrix
#define AT_STAGE (4 * AT_KVB)                 // 36864
#define ATT_SMEM (2 * AT_QB + 2 * AT_STAGE)   // 110592

__global__ __launch_bounds__(256, 1) void attn_mma_kernel()
{
    extern __shared__ char sm[];
    const uint32_t sb = smem_u32(sm);
    const int tid = threadIdx.x, wid = tid >> 5, lid = tid & 31;
    const int qx = (int)gridDim.x - 1 - (int)blockIdx.x;  // heavy tiles first
    const int bh = blockIdx.y;
    const int q0 = qx << 7;
    const int ntiles = 2 * qx + 2;

    const __nv_bfloat16* qhp = g_qh + (size_t)bh * SS * HD;
    const __nv_bfloat16* qlp = g_ql + (size_t)bh * SS * HD;
    const __nv_bfloat16* khp = g_kh + (size_t)bh * SS * HD;
    const __nv_bfloat16* klp = g_kl + (size_t)bh * SS * HD;
    const __nv_bfloat16* vhp = g_vth + (size_t)bh * HD * SS;
    const __nv_bfloat16* vlp = g_vtl + (size_t)bh * HD * SS;

    const uint32_t sQh = sb, sQl = sb + AT_QB;
    const uint32_t sKV = sb + 2 * AT_QB;

    // Q tiles (hi+lo): 128 rows x 8 chunks of 16B each
#pragma unroll
    for (int it = 0; it < 4; it++) {
        int idx = tid + it * 256;
        int r = idx >> 3, c = idx & 7;
        cp_async16(sQh + r * AT_ROWB + c * 16, qhp + (size_t)(q0 + r) * HD + c * 8);
        cp_async16(sQl + r * AT_ROWB + c * 16, qlp + (size_t)(q0 + r) * HD + c * 8);
    }
    CP_COMMIT();

    auto issue_kv = [&](int kt) {
        const uint32_t st = sKV + (uint32_t)(kt & 1) * AT_STAGE;
        const int kv0 = kt << 6;
#pragma unroll
        for (int it = 0; it < 2; it++) {
            int idx = tid + it * 256;
            int r = idx >> 3, c = idx & 7;
            cp_async16(st + 0 * AT_KVB + r * AT_ROWB + c * 16,
                       khp + (size_t)(kv0 + r) * HD + c * 8);
            cp_async16(st + 1 * AT_KVB + r * AT_ROWB + c * 16,
                       klp + (size_t)(kv0 + r) * HD + c * 8);
            cp_async16(st + 2 * AT_KVB + r * AT_ROWB + c * 16,
                       vhp + (size_t)r * SS + kv0 + c * 8);
            cp_async16(st + 3 * AT_KVB + r * AT_ROWB + c * 16,
                       vlp + (size_t)r * SS + kv0 + c * 8);
        }
        CP_COMMIT();
    };
    issue_kv(0);

    uint32_t qfh[4][4], qfl[4][4];
    float oacc[8][4];
#pragma unroll
    for (int nt = 0; nt < 8; nt++)
#pragma unroll
        for (int e = 0; e < 4; e++) oacc[nt][e] = 0.f;
    float m0 = -INFINITY, m1 = -INFINITY, l0 = 0.f, l1 = 0.f;

    const uint32_t bg = lid >> 3, brl = lid & 7;
    const int r0 = q0 + wid * 16 + (lid >> 2);   // thread row (r1 = r0 + 8)

    for (int kt = 0; kt < ntiles; kt++) {
        if (kt + 1 < ntiles) { issue_kv(kt + 1); cp_wait<1>(); }
        else cp_wait<0>();
        __syncthreads();

        if (kt == 0) {
            const uint32_t arow = (uint32_t)(wid * 16 + (lid & 15));
            const uint32_t aoff = (lid & 16) ? 16u : 0u;
#pragma unroll
            for (int kc = 0; kc < 4; kc++) {
                ldmatrix_x4(qfh[kc], sQh + arow * AT_ROWB + kc * 32 + aoff);
                ldmatrix_x4(qfl[kc], sQl + arow * AT_ROWB + kc * 32 + aoff);
            }
        }

        const uint32_t st = sKV + (uint32_t)(kt & 1) * AT_STAGE;
        const int kv0 = kt << 6;

        // ---- S = Q K^T (split bf16) ----
        float sacc[8][4];
#pragma unroll
        for (int nt = 0; nt < 8; nt++)
#pragma unroll
            for (int e = 0; e < 4; e++) sacc[nt][e] = 0.f;

#pragma unroll
        for (int kc = 0; kc < 4; kc++) {
            uint32_t kbh[8][2], kbl[8][2];
            const uint32_t off = kc * 32 + ((bg & 1) ? 16 : 0);
#pragma unroll
            for (int g = 0; g < 4; g++) {
                uint32_t nrow = g * 16 + ((bg & 2) ? 8 : 0) + brl;
                uint32_t tmp[4];
                ldmatrix_x4(tmp, st + 0 * AT_KVB + nrow * AT_ROWB + off);
                kbh[2 * g][0] = tmp[0]; kbh[2 * g][1] = tmp[1];
                kbh[2 * g + 1][0] = tmp[2]; kbh[2 * g + 1][1] = tmp[3];
                ldmatrix_x4(tmp, st + 1 * AT_KVB + nrow * AT_ROWB + off);
                kbl[2 * g][0] = tmp[0]; kbl[2 * g][1] = tmp[1];
                kbl[2 * g + 1][0] = tmp[2]; kbl[2 * g + 1][1] = tmp[3];
            }
#pragma unroll
            for (int nt = 0; nt < 8; nt++) {
                mma_bf16(sacc[nt], qfh[kc], kbh[nt]);
                mma_bf16(sacc[nt], qfl[kc], kbh[nt]);
                mma_bf16(sacc[nt], qfh[kc], kbl[nt]);
            }
        }

        // ---- scale + causal mask ----
        const bool need_mask = (kv0 + 63 > q0 + wid * 16);
#pragma unroll
        for (int nt = 0; nt < 8; nt++) {
#pragma unroll
            for (int e = 0; e < 4; e++) sacc[nt][e] *= 0.125f;
        }
        if (need_mask) {
#pragma unroll
            for (int nt = 0; nt < 8; nt++) {
                int c = kv0 + nt * 8 + ((lid & 3) << 1);
                if (c > r0)         sacc[nt][0] = -1e10f;
                if (c + 1 > r0)     sacc[nt][1] = -1e10f;
                if (c > r0 + 8)     sacc[nt][2] = -1e10f;
                if (c + 1 > r0 + 8) sacc[nt][3] = -1e10f;
            }
        }

        // ---- online softmax (rows r0, r0+8) ----
        float mx0 = -INFINITY, mx1 = -INFINITY;
#pragma unroll
        for (int nt = 0; nt < 8; nt++) {
            mx0 = fmaxf(mx0, fmaxf(sacc[nt][0], sacc[nt][1]));
            mx1 = fmaxf(mx1, fmaxf(sacc[nt][2], sacc[nt][3]));
        }
        mx0 = fmaxf(mx0, __shfl_xor_sync(0xffffffffu, mx0, 1));
        mx0 = fmaxf(mx0, __shfl_xor_sync(0xffffffffu, mx0, 2));
        mx1 = fmaxf(mx1, __shfl_xor_sync(0xffffffffu, mx1, 1));
        mx1 = fmaxf(mx1, __shfl_xor_sync(0xffffffffu, mx1, 2));
        float mn0 = fmaxf(m0, mx0), mn1 = fmaxf(m1, mx1);
        float alpha0 = __expf(m0 - mn0), alpha1 = __expf(m1 - mn1);
        float s0 = 0.f, s1 = 0.f;
#pragma unroll
        for (int nt = 0; nt < 8; nt++) {
            sacc[nt][0] = __expf(sacc[nt][0] - mn0);
            sacc[nt][1] = __expf(sacc[nt][1] - mn0);
            sacc[nt][2] = __expf(sacc[nt][2] - mn1);
            sacc[nt][3] = __expf(sacc[nt][3] - mn1);
            s0 += sacc[nt][0] + sacc[nt][1];
            s1 += sacc[nt][2] + sacc[nt][3];
        }
        s0 += __shfl_xor_sync(0xffffffffu, s0, 1);
        s0 += __shfl_xor_sync(0xffffffffu, s0, 2);
        s1 += __shfl_xor_sync(0xffffffffu, s1, 1);
        s1 += __shfl_xor_sync(0xffffffffu, s1, 2);
        l0 = l0 * alpha0 + s0;
        l1 = l1 * alpha1 + s1;
        m0 = mn0; m1 = mn1;
#pragma unroll
        for (int nt = 0; nt < 8; nt++) {
            oacc[nt][0] *= alpha0; oacc[nt][1] *= alpha0;
            oacc[nt][2] *= alpha1; oacc[nt][3] *= alpha1;
        }

        // ---- O += P V (P repacked to A-frags, split hi/lo) ----
#pragma unroll
        for (int c = 0; c < 4; c++) {
            uint32_t pha[4], pla[4];
            split2(sacc[2 * c][0], sacc[2 * c][1], pha[0], pla[0]);
            split2(sacc[2 * c][2], sacc[2 * c][3], pha[1], pla[1]);
            split2(sacc[2 * c + 1][0], sacc[2 * c + 1][1], pha[2], pla[2]);
            split2(sacc[2 * c + 1][2], sacc[2 * c + 1][3], pha[3], pla[3]);

            uint32_t vbh[8][2], vbl[8][2];
            const uint32_t off = c * 32 + ((bg & 1) ? 16 : 0);
#pragma unroll
            for (int g = 0; g < 4; g++) {
                uint32_t nrow = g * 16 + ((bg & 2) ? 8 : 0) + brl;
                uint32_t tmp[4];
                ldmatrix_x4(tmp, st + 2 * AT_KVB + nrow * AT_ROWB + off);
                vbh[2 * g][0] = tmp[0]; vbh[2 * g][1] = tmp[1];
                vbh[2 * g + 1][0] = tmp[2]; vbh[2 * g + 1][1] = tmp[3];
                ldmatrix_x4(tmp, st + 3 * AT_KVB + nrow * AT_ROWB + off);
                vbl[2 * g][0] = tmp[0]; vbl[2 * g][1] = tmp[1];
                vbl[2 * g + 1][0] = tmp[2]; vbl[2 * g + 1][1] = tmp[3];
            }
#pragma unroll
            for (int nt = 0; nt < 8; nt++) {
                mma_bf16(oacc[nt], pha, vbh[nt]);
                mma_bf16(oacc[nt], pla, vbh[nt]);
                mma_bf16(oacc[nt], pha, vbl[nt]);
            }
        }
        __syncthreads();
    }

    // ---- epilogue: normalize, write bf16 hi/lo att ----
    const float inv0 = 1.f / l0, inv1 = 1.f / l1;
    const int b = bh >> 4, h = bh & 15;
#pragma unroll
    for (int nt = 0; nt < 8; nt++) {
        const int d = h * 64 + nt * 8 + ((lid & 3) << 1);
        uint32_t hi, lo;
        split2(oacc[nt][0] * inv0, oacc[nt][1] * inv0, hi, lo);
        size_t base0 = ((size_t)(b * SS + r0)) * DD + d;
        *reinterpret_cast<uint32_t*>(g_atth + base0) = hi;
        *reinterpret_cast<uint32_t*>(g_attl + base0) = lo;
        split2(oacc[nt][2] * inv1, oacc[nt][3] * inv1, hi, lo);
        size_t base1 = ((size_t)(b * SS + r0 + 8)) * DD + d;
        *reinterpret_cast<uint32_t*>(g_atth + base1) = hi;
        *reinterpret_cast<uint32_t*>(g_attl + base1) = lo;
    }
}

// ---------------------------------------------------------------------------
// Top-8 tiles from last token (tile-max logits — monotone w/ softmax probs)
// ---------------------------------------------------------------------------
__global__ __launch_bounds__(256) void topk_kernel(float* __restrict__ out_idx)
{
    __shared__ float qsh[64];
    __shared__ float ls[2048];
    __shared__ float tile[128];
    const int bh = blockIdx.x;
    const int tid = threadIdx.x;
    const size_t qoff = ((size_t)bh * SS + (SS - 1)) * HD;
    if (tid < 64)
        qsh[tid] = __bfloat162float(g_qh[qoff + tid]) +
                   __bfloat162float(g_ql[qoff + tid]);
    __syncthreads();
    const size_t kbase = (size_t)bh * SS * HD;
    for (int k = tid; k < SS; k += 256) {
        const uint32_t* krh = reinterpret_cast<const uint32_t*>(g_kh + kbase + (size_t)k * HD);
        const uint32_t* krl = reinterpret_cast<const uint32_t*>(g_kl + kbase + (size_t)k * HD);
        float acc = 0.f;
#pragma unroll
        for (int d2 = 0; d2 < 32; d2++) {
            uint32_t uh = krh[d2], ul = krl[d2];
            __nv_bfloat162 bh2 = *reinterpret_cast<__nv_bfloat162*>(&uh);
            __nv_bfloat162 bl2 = *reinterpret_cast<__nv_bfloat162*>(&ul);
            float k0 = __bfloat162float(bh2.x) + __bfloat162float(bl2.x);
            float k1 = __bfloat162float(bh2.y) + __bfloat162float(bl2.y);
            acc = fmaf(qsh[d2 * 2], k0, acc);
            acc = fmaf(qsh[d2 * 2 + 1], k1, acc);
        }
        ls[k] = acc;
    }
    __syncthreads();
    if (tid < 128) {
        float m = -INFINITY;
#pragma unroll
        for (int e = 0; e < 16; e++) m = fmaxf(m, ls[tid * 16 + e]);
        tile[tid] = m;
    }
    __syncthreads();
    if (tid == 0) {
        for (int slot = 0; slot < 8; slot++) {
            float best = -INFINITY; int bi = 0;
            for (int t = 0; t < 128; t++)
                if (tile[t] > best) { best = tile[t]; bi = t; }
            tile[bi] = -INFINITY;
            out_idx[bh * 8 + slot] = (float)bi;
        }
    }
}

// ---------------------------------------------------------------------------
extern "C" void kernel_launch(void* const* d_in, const int* in_sizes, int n_in,
                              void* d_out, int out_size)
{
    const float* x  = (const float*)d_in[0];
    const float* wq = (const float*)d_in[1];
    const float* wk = (const float*)d_in[2];
    const float* wv = (const float*)d_in[3];
    const float* wo = (const float*)d_in[4];
    float* out = (float*)d_out;

    cudaFuncSetAttribute(mma_gemm_kernel,
                         cudaFuncAttributeMaxDynamicSharedMemorySize, GEMM_SMEM_BYTES);
    cudaFuncSetAttribute(attn_mma_kernel,
                         cudaFuncAttributeMaxDynamicSharedMemorySize, ATT_SMEM);

    // prep
    convert_x_kernel<<<(MM * DD) / 4 / 256, 256>>>(x);
    transpose_w_kernel<<<dim3(32, 32, 4), dim3(32, 8)>>>(wq, wk, wv, wo);
    rope_table_kernel<<<SS, 32>>>();

    // QKV GEMM + RoPE (HMMA)
    mma_gemm_kernel<<<dim3(24, 32), 256, GEMM_SMEM_BYTES>>>(0, nullptr);

    // top-k tiles
    topk_kernel<<<32, 256>>>(out + (size_t)MM * DD);

    // flash attention (HMMA)
    attn_mma_kernel<<<dim3(16, 32), 256, ATT_SMEM>>>();

    // output projection (HMMA)
    mma_gemm_kernel<<<dim3(8, 32), 256, GEMM_SMEM_BYTES>>>(1, out);
}

// round 7
// speedup vs baseline: 2.4221x; 1.0267x over previous
#include <cuda_runtime.h>
#include <cuda_bf16.h>
#include <math.h>
#include <stdint.h>

#define BB 2
#define SS 2048
#define DD 1024
#define NH 16
#define HD 64
#define MM (BB*SS)

// ---------------------------------------------------------------------------
// Device scratch (allocation-free rule). Referenced ONLY from device code.
// ---------------------------------------------------------------------------
__device__ __nv_bfloat16 g_xh[(size_t)MM*DD];
__device__ __nv_bfloat16 g_xl[(size_t)MM*DD];
__device__ __nv_bfloat16 g_wqkvt_h[(size_t)3*DD*DD];   // [3072 n][1024 k]
__device__ __nv_bfloat16 g_wqkvt_l[(size_t)3*DD*DD];
__device__ __nv_bfloat16 g_wot_h[(size_t)DD*DD];       // [1024 n][1024 k]
__device__ __nv_bfloat16 g_wot_l[(size_t)DD*DD];
__device__ __nv_bfloat16 g_qh[(size_t)BB*NH*SS*HD];    // [bh][s][d]
__device__ __nv_bfloat16 g_ql[(size_t)BB*NH*SS*HD];
__device__ __nv_bfloat16 g_kh[(size_t)BB*NH*SS*HD];
__device__ __nv_bfloat16 g_kl[(size_t)BB*NH*SS*HD];
__device__ __nv_bfloat16 g_vth[(size_t)BB*NH*HD*SS];   // [bh][d][s] transposed
__device__ __nv_bfloat16 g_vtl[(size_t)BB*NH*HD*SS];
__device__ __nv_bfloat16 g_atth[(size_t)MM*DD];
__device__ __nv_bfloat16 g_attl[(size_t)MM*DD];
__device__ float2 g_rope[(size_t)SS*32];               // cos,sin per (s, d/2)

// ---------------------------------------------------------------------------
// PTX helpers (base ISA only — must compile for plain compute_103)
// ---------------------------------------------------------------------------
__device__ __forceinline__ uint32_t smem_u32(const void* p) {
    uint32_t a;
    asm("{ .reg .u64 t; cvta.to.shared.u64 t, %1; cvt.u32.u64 %0, t; }"
        : "=r"(a) : "l"(p));
    return a;
}
__device__ __forceinline__ void cp_async16(uint32_t dst, const void* src) {
    asm volatile("{\n .reg .u64 g;\n cvta.to.global.u64 g, %1;\n"
                 " cp.async.cg.shared.global [%0], [g], 16;\n}"
                 :: "r"(dst), "l"(src) : "memory");
}
#define CP_COMMIT() asm volatile("cp.async.commit_group;" ::: "memory")
template <int N>
__device__ __forceinline__ void cp_wait() {
    asm volatile("cp.async.wait_group %0;" :: "n"(N) : "memory");
}
__device__ __forceinline__ void ldmatrix_x4(uint32_t* r, uint32_t addr) {
    asm volatile("ldmatrix.sync.aligned.m8n8.x4.shared.b16 {%0,%1,%2,%3}, [%4];"
                 : "=r"(r[0]), "=r"(r[1]), "=r"(r[2]), "=r"(r[3]) : "r"(addr));
}
__device__ __forceinline__ void mma_bf16(float* d, const uint32_t* a, const uint32_t* b) {
    asm volatile(
        "mma.sync.aligned.m16n8k16.row.col.f32.bf16.bf16.f32 "
        "{%0,%1,%2,%3}, {%4,%5,%6,%7}, {%8,%9}, {%0,%1,%2,%3};"
        : "+f"(d[0]), "+f"(d[1]), "+f"(d[2]), "+f"(d[3])
        : "r"(a[0]), "r"(a[1]), "r"(a[2]), "r"(a[3]), "r"(b[0]), "r"(b[1]));
}
// pack two fp32 -> bf16x2 hi + residual-lo words
__device__ __forceinline__ void split2(float a, float b, uint32_t& hi, uint32_t& lo) {
    __nv_bfloat16 ah = __float2bfloat16(a), bh = __float2bfloat16(b);
    __nv_bfloat162 h; h.x = ah; h.y = bh;
    __nv_bfloat162 l;
    l.x = __float2bfloat16(a - __bfloat162float(ah));
    l.y = __float2bfloat16(b - __bfloat162float(bh));
    hi = *reinterpret_cast<uint32_t*>(&h);
    lo = *reinterpret_cast<uint32_t*>(&l);
}

// ---------------------------------------------------------------------------
// Prep kernel A: x -> bf16 hi/lo
// ---------------------------------------------------------------------------
__global__ __launch_bounds__(256) void convert_x_kernel(const float* __restrict__ x)
{
    size_t idx = (size_t)blockIdx.x * 256 + threadIdx.x;   // one float4
    float4 v = reinterpret_cast<const float4*>(x)[idx];
    uint32_t h0, l0, h1, l1;
    split2(v.x, v.y, h0, l0);
    split2(v.z, v.w, h1, l1);
    reinterpret_cast<uint32_t*>(g_xh)[idx * 2 + 0] = h0;
    reinterpret_cast<uint32_t*>(g_xh)[idx * 2 + 1] = h1;
    reinterpret_cast<uint32_t*>(g_xl)[idx * 2 + 0] = l0;
    reinterpret_cast<uint32_t*>(g_xl)[idx * 2 + 1] = l1;
}

// ---------------------------------------------------------------------------
// Prep kernel B: transpose weights -> N-major bf16 hi/lo
// ---------------------------------------------------------------------------
__global__ __launch_bounds__(256) void transpose_w_kernel(
    const float* __restrict__ wq, const float* __restrict__ wk,
    const float* __restrict__ wv, const float* __restrict__ wo)
{
    __shared__ float tile[32][33];
    const int mat = blockIdx.z;
    const float* src = (mat == 0) ? wq : (mat == 1) ? wk : (mat == 2) ? wv : wo;
    const int k0 = blockIdx.y * 32, n0 = blockIdx.x * 32;
    const int tx = threadIdx.x, ty = threadIdx.y;     // 32 x 8
#pragma unroll
    for (int i = 0; i < 32; i += 8)
        tile[ty + i][tx] = src[(size_t)(k0 + ty + i) * DD + n0 + tx];
    __syncthreads();
    __nv_bfloat16* dh;
    __nv_bfloat16* dl;
    size_t rowoff;
    if (mat < 3) { dh = g_wqkvt_h; dl = g_wqkvt_l; rowoff = (size_t)mat * DD; }
    else         { dh = g_wot_h;   dl = g_wot_l;   rowoff = 0; }
#pragma unroll
    for (int i = 0; i < 32; i += 8) {
        float v = tile[tx][ty + i];                   // = w[k0+tx][n0+ty+i]
        __nv_bfloat16 h = __float2bfloat16(v);
        __nv_bfloat16 l = __float2bfloat16(v - __bfloat162float(h));
        size_t di = (rowoff + n0 + ty + i) * DD + k0 + tx;
        dh[di] = h;
        dl[di] = l;
    }
}

// ---------------------------------------------------------------------------
// Prep kernel C: RoPE cos/sin table
// ---------------------------------------------------------------------------
__global__ void rope_table_kernel()
{
    int s = blockIdx.x;
    int dp = threadIdx.x;    // 0..31, pair index
    float inv = expf(-0.14391156831212807f * (float)(2 * dp));
    float ang = (float)s * inv;
    float sn, cs;
    sincosf(ang, &sn, &cs);
    g_rope[s * 32 + dp] = make_float2(cs, sn);
}

// ---------------------------------------------------------------------------
// HMMA GEMM (split bf16): mode 0 = QKV+RoPE, mode 1 = out-proj.
// 2 CTAs/SM target: regs capped at 128, B-frags loaded per nt-pair.
// ---------------------------------------------------------------------------
#define ROWB 80                     // smem row stride bytes (rows hold 32 bf16)
#define MATB (128 * ROWB)           // 10240 bytes per matrix tile
#define STGB (4 * MATB)             // 40960 per stage
#define GEMM_SMEM_BYTES (2 * STGB)  // 81920

__global__ __launch_bounds__(256, 2) void mma_gemm_kernel(
    int mode, float* __restrict__ outp)
{
    extern __shared__ char sm[];
    const uint32_t sb = smem_u32(sm);
    const int tid = threadIdx.x, wid = tid >> 5, lid = tid & 31;
    const int m0 = blockIdx.y << 7, n0 = blockIdx.x << 7;
    const int wm = wid & 1, wn = wid >> 1;

    const __nv_bfloat16* __restrict__ Ah = (mode == 0) ? g_xh : g_atth;
    const __nv_bfloat16* __restrict__ Al = (mode == 0) ? g_xl : g_attl;
    const __nv_bfloat16* __restrict__ Bh = (mode == 0) ? g_wqkvt_h : g_wot_h;
    const __nv_bfloat16* __restrict__ Bl = (mode == 0) ? g_wqkvt_l : g_wot_l;

    float acc[4][4][4];
#pragma unroll
    for (int i = 0; i < 4; i++)
#pragma unroll
        for (int j = 0; j < 4; j++)
#pragma unroll
            for (int r = 0; r < 4; r++) acc[i][j][r] = 0.f;

    const int ld_r = tid >> 2;
    const int ld_c = tid & 3;

    auto issue_stage = [&](int t, int stg) {
        const int k0 = t << 5;
        const uint32_t dst0 = sb + (uint32_t)stg * STGB;
#pragma unroll
        for (int q = 0; q < 4; q++) {
            const __nv_bfloat16* S = (q == 0) ? Ah : (q == 1) ? Al : (q == 2) ? Bh : Bl;
            const int rbase = (q < 2) ? m0 : n0;
#pragma unroll
            for (int half = 0; half < 2; half++) {
                int r = ld_r + half * 64;
                cp_async16(dst0 + q * MATB + r * ROWB + ld_c * 16,
                           S + (size_t)(rbase + r) * DD + k0 + ld_c * 8);
            }
        }
    };

    issue_stage(0, 0);
    CP_COMMIT();

    for (int t = 0; t < 32; t++) {
        if (t + 1 < 32) {
            issue_stage(t + 1, (t + 1) & 1);
            CP_COMMIT();
            cp_wait<1>();
        } else {
            cp_wait<0>();
        }
        __syncthreads();

        const uint32_t stg = sb + (uint32_t)(t & 1) * STGB;
        const uint32_t sAh = stg, sAl = stg + MATB;
        const uint32_t sBh = stg + 2 * MATB, sBl = stg + 3 * MATB;

        const uint32_t bg = lid >> 3, brl = lid & 7;

#pragma unroll
        for (int ks = 0; ks < 2; ks++) {
            uint32_t ah[4][4], al[4][4];
            const uint32_t akb = ks * 32 + ((lid & 16) ? 16 : 0);
            const uint32_t arow = wm * 64 + (lid & 15);
#pragma unroll
            for (int mt = 0; mt < 4; mt++) {
                ldmatrix_x4(ah[mt], sAh + (arow + mt * 16) * ROWB + akb);
                ldmatrix_x4(al[mt], sAl + (arow + mt * 16) * ROWB + akb);
            }
            const uint32_t bkb = ks * 32 + ((bg & 1) ? 16 : 0);
            // B frags per nt-pair, interleaved with MMAs (lower reg pressure)
#pragma unroll
            for (int p = 0; p < 2; p++) {
                const uint32_t nrow = wn * 32 + p * 16 + ((bg & 2) ? 8 : 0) + brl;
                uint32_t th[4], tl[4];
                ldmatrix_x4(th, sBh + nrow * ROWB + bkb);
                ldmatrix_x4(tl, sBl + nrow * ROWB + bkb);
#pragma unroll
                for (int mt = 0; mt < 4; mt++) {
                    mma_bf16(acc[mt][2 * p], ah[mt], th);
                    mma_bf16(acc[mt][2 * p], al[mt], th);
                    mma_bf16(acc[mt][2 * p], ah[mt], tl);
                    mma_bf16(acc[mt][2 * p + 1], ah[mt], th + 2);
                    mma_bf16(acc[mt][2 * p + 1], al[mt], th + 2);
                    mma_bf16(acc[mt][2 * p + 1], ah[mt], tl + 2);
                }
            }
        }
        __syncthreads();
    }

    // Epilogue
#pragma unroll
    for (int mt = 0; mt < 4; mt++) {
#pragma unroll
        for (int nt = 0; nt < 4; nt++) {
            const int row = m0 + wm * 64 + mt * 16 + (lid >> 2);
            const int col = n0 + wn * 32 + nt * 8 + ((lid & 3) << 1);
#pragma unroll
            for (int half = 0; half < 2; half++) {
                const int r = row + half * 8;
                float v0 = acc[mt][nt][half * 2 + 0];
                float v1 = acc[mt][nt][half * 2 + 1];
                if (mode == 0) {
                    const int which = col >> 10;
                    const int nn = col & 1023;
                    const int h = nn >> 6, d = nn & 63;
                    const int b = r >> 11, s = r & 2047;
                    const size_t bh = (size_t)(b * NH + h);
                    if (which < 2) {
                        float2 cs = g_rope[s * 32 + (d >> 1)];
                        float r0 = v0 * cs.x - v1 * cs.y;
                        float r1 = v0 * cs.y + v1 * cs.x;
                        v0 = r0; v1 = r1;
                        uint32_t hi, lo;
                        split2(v0, v1, hi, lo);
                        size_t base = (bh * SS + s) * HD + d;
                        __nv_bfloat16* dh = (which == 0) ? g_qh : g_kh;
                        __nv_bfloat16* dl = (which == 0) ? g_ql : g_kl;
                        *reinterpret_cast<uint32_t*>(dh + base) = hi;
                        *reinterpret_cast<uint32_t*>(dl + base) = lo;
                    } else {
                        // V: transposed bf16 hi/lo [bh][d][s]
                        __nv_bfloat16 h0 = __float2bfloat16(v0);
                        __nv_bfloat16 h1 = __float2bfloat16(v1);
                        size_t vb = (bh * HD + d) * SS + s;
                        g_vth[vb] = h0;
                        g_vth[vb + SS] = h1;
                        g_vtl[vb] = __float2bfloat16(v0 - __bfloat162float(h0));
                        g_vtl[vb + SS] = __float2bfloat16(v1 - __bfloat162float(h1));
                    }
                } else {
                    *reinterpret_cast<float2*>(outp + (size_t)r * DD + col) =
                        make_float2(v0, v1);
                }
            }
        }
    }
}

// ---------------------------------------------------------------------------
// HMMA flash attention. CTA = 128 q rows x (b,h). 8 warps (warp = m16).
// KV tiles of 64, cp.async double-buffered. Split-bf16 for QK^T and PV.
// Rows hold HD=64 bf16 = 128 bytes -> row stride 144 bytes (pad 16).
// 2 CTAs/SM target: regs capped at 128, K/V frags loaded per nt-pair.
// ---------------------------------------------------------------------------
#define AT_ROWB 144
#define AT_QB (128 * AT_ROWB)                 // 18432 per Q matrix
#define AT_KVB (64 * AT_ROWB)                 // 9216 per KV matrix
#define AT_STAGE (4 * AT_KVB)                 // 36864
#define ATT_SMEM (2 * AT_QB + 2 * AT_STAGE)   // 110592

__global__ __launch_bounds__(256, 2) void attn_mma_kernel()
{
    extern __shared__ char sm[];
    const uint32_t sb = smem_u32(sm);
    const int tid = threadIdx.x, wid = tid >> 5, lid = tid & 31;
    const int qx = (int)gridDim.x - 1 - (int)blockIdx.x;  // heavy tiles first
    const int bh = blockIdx.y;
    const int q0 = qx << 7;
    const int ntiles = 2 * qx + 2;

    const __nv_bfloat16* qhp = g_qh + (size_t)bh * SS * HD;
    const __nv_bfloat16* qlp = g_ql + (size_t)bh * SS * HD;
    const __nv_bfloat16* khp = g_kh + (size_t)bh * SS * HD;
    const __nv_bfloat16* klp = g_kl + (size_t)bh * SS * HD;
    const __nv_bfloat16* vhp = g_vth + (size_t)bh * HD * SS;
    const __nv_bfloat16* vlp = g_vtl + (size_t)bh * HD * SS;

    const uint32_t sQh = sb, sQl = sb + AT_QB;
    const uint32_t sKV = sb + 2 * AT_QB;

    // Q tiles (hi+lo): 128 rows x 8 chunks of 16B each
#pragma unroll
    for (int it = 0; it < 4; it++) {
        int idx = tid + it * 256;
        int r = idx >> 3, c = idx & 7;
        cp_async16(sQh + r * AT_ROWB + c * 16, qhp + (size_t)(q0 + r) * HD + c * 8);
        cp_async16(sQl + r * AT_ROWB + c * 16, qlp + (size_t)(q0 + r) * HD + c * 8);
    }
    CP_COMMIT();

    auto issue_kv = [&](int kt) {
        const uint32_t st = sKV + (uint32_t)(kt & 1) * AT_STAGE;
        const int kv0 = kt << 6;
#pragma unroll
        for (int it = 0; it < 2; it++) {
            int idx = tid + it * 256;
            int r = idx >> 3, c = idx & 7;
            cp_async16(st + 0 * AT_KVB + r * AT_ROWB + c * 16,
                       khp + (size_t)(kv0 + r) * HD + c * 8);
            cp_async16(st + 1 * AT_KVB + r * AT_ROWB + c * 16,
                       klp + (size_t)(kv0 + r) * HD + c * 8);
            cp_async16(st + 2 * AT_KVB + r * AT_ROWB + c * 16,
                       vhp + (size_t)r * SS + kv0 + c * 8);
            cp_async16(st + 3 * AT_KVB + r * AT_ROWB + c * 16,
                       vlp + (size_t)r * SS + kv0 + c * 8);
        }
        CP_COMMIT();
    };
    issue_kv(0);

    uint32_t qfh[4][4], qfl[4][4];
    float oacc[8][4];
#pragma unroll
    for (int nt = 0; nt < 8; nt++)
#pragma unroll
        for (int e = 0; e < 4; e++) oacc[nt][e] = 0.f;
    float m0 = -INFINITY, m1 = -INFINITY, l0 = 0.f, l1 = 0.f;

    const uint32_t bg = lid >> 3, brl = lid & 7;
    const int r0 = q0 + wid * 16 + (lid >> 2);   // thread row (r1 = r0 + 8)

    for (int kt = 0; kt < ntiles; kt++) {
        if (kt + 1 < ntiles) { issue_kv(kt + 1); cp_wait<1>(); }
        else cp_wait<0>();
        __syncthreads();

        if (kt == 0) {
            const uint32_t arow = (uint32_t)(wid * 16 + (lid & 15));
            const uint32_t aoff = (lid & 16) ? 16u : 0u;
#pragma unroll
            for (int kc = 0; kc < 4; kc++) {
                ldmatrix_x4(qfh[kc], sQh + arow * AT_ROWB + kc * 32 + aoff);
                ldmatrix_x4(qfl[kc], sQl + arow * AT_ROWB + kc * 32 + aoff);
            }
        }

        const uint32_t st = sKV + (uint32_t)(kt & 1) * AT_STAGE;
        const int kv0 = kt << 6;

        // ---- S = Q K^T (split bf16); K frags per nt-pair ----
        float sacc[8][4];
#pragma unroll
        for (int nt = 0; nt < 8; nt++)
#pragma unroll
            for (int e = 0; e < 4; e++) sacc[nt][e] = 0.f;

#pragma unroll
        for (int kc = 0; kc < 4; kc++) {
            const uint32_t off = kc * 32 + ((bg & 1) ? 16 : 0);
#pragma unroll
            for (int g = 0; g < 4; g++) {
                const uint32_t nrow = g * 16 + ((bg & 2) ? 8 : 0) + brl;
                uint32_t th[4], tl[4];
                ldmatrix_x4(th, st + 0 * AT_KVB + nrow * AT_ROWB + off);
                ldmatrix_x4(tl, st + 1 * AT_KVB + nrow * AT_ROWB + off);
                mma_bf16(sacc[2 * g], qfh[kc], th);
                mma_bf16(sacc[2 * g], qfl[kc], th);
                mma_bf16(sacc[2 * g], qfh[kc], tl);
                mma_bf16(sacc[2 * g + 1], qfh[kc], th + 2);
                mma_bf16(sacc[2 * g + 1], qfl[kc], th + 2);
                mma_bf16(sacc[2 * g + 1], qfh[kc], tl + 2);
            }
        }

        // ---- scale + causal mask ----
        const bool need_mask = (kv0 + 63 > q0 + wid * 16);
#pragma unroll
        for (int nt = 0; nt < 8; nt++) {
#pragma unroll
            for (int e = 0; e < 4; e++) sacc[nt][e] *= 0.125f;
        }
        if (need_mask) {
#pragma unroll
            for (int nt = 0; nt < 8; nt++) {
                int c = kv0 + nt * 8 + ((lid & 3) << 1);
                if (c > r0)         sacc[nt][0] = -1e10f;
                if (c + 1 > r0)     sacc[nt][1] = -1e10f;
                if (c > r0 + 8)     sacc[nt][2] = -1e10f;
                if (c + 1 > r0 + 8) sacc[nt][3] = -1e10f;
            }
        }

        // ---- online softmax (rows r0, r0+8) ----
        float mx0 = -INFINITY, mx1 = -INFINITY;
#pragma unroll
        for (int nt = 0; nt < 8; nt++) {
            mx0 = fmaxf(mx0, fmaxf(sacc[nt][0], sacc[nt][1]));
            mx1 = fmaxf(mx1, fmaxf(sacc[nt][2], sacc[nt][3]));
        }
        mx0 = fmaxf(mx0, __shfl_xor_sync(0xffffffffu, mx0, 1));
        mx0 = fmaxf(mx0, __shfl_xor_sync(0xffffffffu, mx0, 2));
        mx1 = fmaxf(mx1, __shfl_xor_sync(0xffffffffu, mx1, 1));
        mx1 = fmaxf(mx1, __shfl_xor_sync(0xffffffffu, mx1, 2));
        float mn0 = fmaxf(m0, mx0), mn1 = fmaxf(m1, mx1);
        float alpha0 = __expf(m0 - mn0), alpha1 = __expf(m1 - mn1);
        float s0 = 0.f, s1 = 0.f;
#pragma unroll
        for (int nt = 0; nt < 8; nt++) {
            sacc[nt][0] = __expf(sacc[nt][0] - mn0);
            sacc[nt][1] = __expf(sacc[nt][1] - mn0);
            sacc[nt][2] = __expf(sacc[nt][2] - mn1);
            sacc[nt][3] = __expf(sacc[nt][3] - mn1);
            s0 += sacc[nt][0] + sacc[nt][1];
            s1 += sacc[nt][2] + sacc[nt][3];
        }
        s0 += __shfl_xor_sync(0xffffffffu, s0, 1);
        s0 += __shfl_xor_sync(0xffffffffu, s0, 2);
        s1 += __shfl_xor_sync(0xffffffffu, s1, 1);
        s1 += __shfl_xor_sync(0xffffffffu, s1, 2);
        l0 = l0 * alpha0 + s0;
        l1 = l1 * alpha1 + s1;
        m0 = mn0; m1 = mn1;
#pragma unroll
        for (int nt = 0; nt < 8; nt++) {
            oacc[nt][0] *= alpha0; oacc[nt][1] *= alpha0;
            oacc[nt][2] *= alpha1; oacc[nt][3] *= alpha1;
        }

        // ---- O += P V (P repacked to A-frags, split hi/lo); V per nt-pair ----
#pragma unroll
        for (int c = 0; c < 4; c++) {
            uint32_t pha[4], pla[4];
            split2(sacc[2 * c][0], sacc[2 * c][1], pha[0], pla[0]);
            split2(sacc[2 * c][2], sacc[2 * c][3], pha[1], pla[1]);
            split2(sacc[2 * c + 1][0], sacc[2 * c + 1][1], pha[2], pla[2]);
            split2(sacc[2 * c + 1][2], sacc[2 * c + 1][3], pha[3], pla[3]);

            const uint32_t off = c * 32 + ((bg & 1) ? 16 : 0);
#pragma unroll
            for (int g = 0; g < 4; g++) {
                const uint32_t nrow = g * 16 + ((bg & 2) ? 8 : 0) + brl;
                uint32_t th[4], tl[4];
                ldmatrix_x4(th, st + 2 * AT_KVB + nrow * AT_ROWB + off);
                ldmatrix_x4(tl, st + 3 * AT_KVB + nrow * AT_ROWB + off);
                mma_bf16(oacc[2 * g], pha, th);
                mma_bf16(oacc[2 * g], pla, th);
                mma_bf16(oacc[2 * g], pha, tl);
                mma_bf16(oacc[2 * g + 1], pha, th + 2);
                mma_bf16(oacc[2 * g + 1], pla, th + 2);
                mma_bf16(oacc[2 * g + 1], pha, tl + 2);
            }
        }
        __syncthreads();
    }

    // ---- epilogue: normalize, write bf16 hi/lo att ----
    const float inv0 = 1.f / l0, inv1 = 1.f / l1;
    const int b = bh >> 4, h = bh & 15;
#pragma unroll
    for (int nt = 0; nt < 8; nt++) {
        const int d = h * 64 + nt * 8 + ((lid & 3) << 1);
        uint32_t hi, lo;
        split2(oacc[nt][0] * inv0, oacc[nt][1] * inv0, hi, lo);
        size_t base0 = ((size_t)(b * SS + r0)) * DD + d;
        *reinterpret_cast<uint32_t*>(g_atth + base0) = hi;
        *reinterpret_cast<uint32_t*>(g_attl + base0) = lo;
        split2(oacc[nt][2] * inv1, oacc[nt][3] * inv1, hi, lo);
        size_t base1 = ((size_t)(b * SS + r0 + 8)) * DD + d;
        *reinterpret_cast<uint32_t*>(g_atth + base1) = hi;
        *reinterpret_cast<uint32_t*>(g_attl + base1) = lo;
    }
}

// ---------------------------------------------------------------------------
// Top-8 tiles from last token (tile-max logits — monotone w/ softmax probs)
// ---------------------------------------------------------------------------
__global__ __launch_bounds__(256) void topk_kernel(float* __restrict__ out_idx)
{
    __shared__ float qsh[64];
    __shared__ float ls[2048];
    __shared__ float tile[128];
    const int bh = blockIdx.x;
    const int tid = threadIdx.x;
    const size_t qoff = ((size_t)bh * SS + (SS - 1)) * HD;
    if (tid < 64)
        qsh[tid] = __bfloat162float(g_qh[qoff + tid]) +
                   __bfloat162float(g_ql[qoff + tid]);
    __syncthreads();
    const size_t kbase = (size_t)bh * SS * HD;
    for (int k = tid; k < SS; k += 256) {
        const uint32_t* krh = reinterpret_cast<const uint32_t*>(g_kh + kbase + (size_t)k * HD);
        const uint32_t* krl = reinterpret_cast<const uint32_t*>(g_kl + kbase + (size_t)k * HD);
        float acc = 0.f;
#pragma unroll
        for (int d2 = 0; d2 < 32; d2++) {
            uint32_t uh = krh[d2], ul = krl[d2];
            __nv_bfloat162 bh2 = *reinterpret_cast<__nv_bfloat162*>(&uh);
            __nv_bfloat162 bl2 = *reinterpret_cast<__nv_bfloat162*>(&ul);
            float k0 = __bfloat162float(bh2.x) + __bfloat162float(bl2.x);
            float k1 = __bfloat162float(bh2.y) + __bfloat162float(bl2.y);
            acc = fmaf(qsh[d2 * 2], k0, acc);
            acc = fmaf(qsh[d2 * 2 + 1], k1, acc);
        }
        ls[k] = acc;
    }
    __syncthreads();
    if (tid < 128) {
        float m = -INFINITY;
#pragma unroll
        for (int e = 0; e < 16; e++) m = fmaxf(m, ls[tid * 16 + e]);
        tile[tid] = m;
    }
    __syncthreads();
    if (tid == 0) {
        for (int slot = 0; slot < 8; slot++) {
            float best = -INFINITY; int bi = 0;
            for (int t = 0; t < 128; t++)
                if (tile[t] > best) { best = tile[t]; bi = t; }
            tile[bi] = -INFINITY;
            out_idx[bh * 8 + slot] = (float)bi;
        }
    }
}

// ---------------------------------------------------------------------------
extern "C" void kernel_launch(void* const* d_in, const int* in_sizes, int n_in,
                              void* d_out, int out_size)
{
    const float* x  = (const float*)d_in[0];
    const float* wq = (const float*)d_in[1];
    const float* wk = (const float*)d_in[2];
    const float* wv = (const float*)d_in[3];
    const float* wo = (const float*)d_in[4];
    float* out = (float*)d_out;

    cudaFuncSetAttribute(mma_gemm_kernel,
                         cudaFuncAttributeMaxDynamicSharedMemorySize, GEMM_SMEM_BYTES);
    cudaFuncSetAttribute(attn_mma_kernel,
                         cudaFuncAttributeMaxDynamicSharedMemorySize, ATT_SMEM);

    // prep
    convert_x_kernel<<<(MM * DD) / 4 / 256, 256>>>(x);
    transpose_w_kernel<<<dim3(32, 32, 4), dim3(32, 8)>>>(wq, wk, wv, wo);
    rope_table_kernel<<<SS, 32>>>();

    // QKV GEMM + RoPE (HMMA)
    mma_gemm_kernel<<<dim3(24, 32), 256, GEMM_SMEM_BYTES>>>(0, nullptr);

    // top-k tiles
    topk_kernel<<<32, 256>>>(out + (size_t)MM * DD);

    // flash attention (HMMA)
    attn_mma_kernel<<<dim3(16, 32), 256, ATT_SMEM>>>();

    // output projection (HMMA)
    mma_gemm_kernel<<<dim3(8, 32), 256, GEMM_SMEM_BYTES>>>(1, out);
}

// round 8
// speedup vs baseline: 2.5993x; 1.0731x over previous
#include <cuda_runtime.h>
#include <cuda_bf16.h>
#include <math.h>
#include <stdint.h>

#define BB 2
#define SS 2048
#define DD 1024
#define NH 16
#define HD 64
#define MM (BB*SS)

// ---------------------------------------------------------------------------
// Device scratch (allocation-free rule). Referenced ONLY from device code.
// ---------------------------------------------------------------------------
__device__ __nv_bfloat16 g_xh[(size_t)MM*DD];
__device__ __nv_bfloat16 g_xl[(size_t)MM*DD];
__device__ __nv_bfloat16 g_wqkvt_h[(size_t)3*DD*DD];   // [3072 n][1024 k]
__device__ __nv_bfloat16 g_wqkvt_l[(size_t)3*DD*DD];
__device__ __nv_bfloat16 g_wot_h[(size_t)DD*DD];       // [1024 n][1024 k]
__device__ __nv_bfloat16 g_wot_l[(size_t)DD*DD];
__device__ __nv_bfloat16 g_qh[(size_t)BB*NH*SS*HD];    // [bh][s][d]
__device__ __nv_bfloat16 g_ql[(size_t)BB*NH*SS*HD];
__device__ __nv_bfloat16 g_kh[(size_t)BB*NH*SS*HD];
__device__ __nv_bfloat16 g_kl[(size_t)BB*NH*SS*HD];
__device__ __nv_bfloat16 g_vth[(size_t)BB*NH*HD*SS];   // [bh][d][s] transposed
__device__ __nv_bfloat16 g_vtl[(size_t)BB*NH*HD*SS];
__device__ __nv_bfloat16 g_atth[(size_t)MM*DD];
__device__ __nv_bfloat16 g_attl[(size_t)MM*DD];
__device__ float2 g_rope[(size_t)SS*32];               // cos,sin per (s, d/2)

// ---------------------------------------------------------------------------
// PTX helpers (base ISA only — must compile for plain compute_103)
// ---------------------------------------------------------------------------
__device__ __forceinline__ uint32_t smem_u32(const void* p) {
    uint32_t a;
    asm("{ .reg .u64 t; cvta.to.shared.u64 t, %1; cvt.u32.u64 %0, t; }"
        : "=r"(a) : "l"(p));
    return a;
}
__device__ __forceinline__ void cp_async16(uint32_t dst, const void* src) {
    asm volatile("{\n .reg .u64 g;\n cvta.to.global.u64 g, %1;\n"
                 " cp.async.cg.shared.global [%0], [g], 16;\n}"
                 :: "r"(dst), "l"(src) : "memory");
}
#define CP_COMMIT() asm volatile("cp.async.commit_group;" ::: "memory")
template <int N>
__device__ __forceinline__ void cp_wait() {
    asm volatile("cp.async.wait_group %0;" :: "n"(N) : "memory");
}
__device__ __forceinline__ void ldmatrix_x4(uint32_t* r, uint32_t addr) {
    asm volatile("ldmatrix.sync.aligned.m8n8.x4.shared.b16 {%0,%1,%2,%3}, [%4];"
                 : "=r"(r[0]), "=r"(r[1]), "=r"(r[2]), "=r"(r[3]) : "r"(addr));
}
__device__ __forceinline__ void mma_bf16(float* d, const uint32_t* a, const uint32_t* b) {
    asm volatile(
        "mma.sync.aligned.m16n8k16.row.col.f32.bf16.bf16.f32 "
        "{%0,%1,%2,%3}, {%4,%5,%6,%7}, {%8,%9}, {%0,%1,%2,%3};"
        : "+f"(d[0]), "+f"(d[1]), "+f"(d[2]), "+f"(d[3])
        : "r"(a[0]), "r"(a[1]), "r"(a[2]), "r"(a[3]), "r"(b[0]), "r"(b[1]));
}
// pack two fp32 -> bf16x2 hi + residual-lo words
__device__ __forceinline__ void split2(float a, float b, uint32_t& hi, uint32_t& lo) {
    __nv_bfloat16 ah = __float2bfloat16(a), bh = __float2bfloat16(b);
    __nv_bfloat162 h; h.x = ah; h.y = bh;
    __nv_bfloat162 l;
    l.x = __float2bfloat16(a - __bfloat162float(ah));
    l.y = __float2bfloat16(b - __bfloat162float(bh));
    hi = *reinterpret_cast<uint32_t*>(&h);
    lo = *reinterpret_cast<uint32_t*>(&l);
}
// SW128 swizzle: XOR 16B-chunk index (bits[6:4]) with bits[9:7]
#define SW(off) ((uint32_t)(off) ^ (((uint32_t)(off) >> 3) & 0x70u))

// ---------------------------------------------------------------------------
// Prep kernel A: x -> bf16 hi/lo
// ---------------------------------------------------------------------------
__global__ __launch_bounds__(256) void convert_x_kernel(const float* __restrict__ x)
{
    size_t idx = (size_t)blockIdx.x * 256 + threadIdx.x;   // one float4
    float4 v = reinterpret_cast<const float4*>(x)[idx];
    uint32_t h0, l0, h1, l1;
    split2(v.x, v.y, h0, l0);
    split2(v.z, v.w, h1, l1);
    reinterpret_cast<uint32_t*>(g_xh)[idx * 2 + 0] = h0;
    reinterpret_cast<uint32_t*>(g_xh)[idx * 2 + 1] = h1;
    reinterpret_cast<uint32_t*>(g_xl)[idx * 2 + 0] = l0;
    reinterpret_cast<uint32_t*>(g_xl)[idx * 2 + 1] = l1;
}

// ---------------------------------------------------------------------------
// Prep kernel B: transpose weights -> N-major bf16 hi/lo
// ---------------------------------------------------------------------------
__global__ __launch_bounds__(256) void transpose_w_kernel(
    const float* __restrict__ wq, const float* __restrict__ wk,
    const float* __restrict__ wv, const float* __restrict__ wo)
{
    __shared__ float tile[32][33];
    const int mat = blockIdx.z;
    const float* src = (mat == 0) ? wq : (mat == 1) ? wk : (mat == 2) ? wv : wo;
    const int k0 = blockIdx.y * 32, n0 = blockIdx.x * 32;
    const int tx = threadIdx.x, ty = threadIdx.y;     // 32 x 8
#pragma unroll
    for (int i = 0; i < 32; i += 8)
        tile[ty + i][tx] = src[(size_t)(k0 + ty + i) * DD + n0 + tx];
    __syncthreads();
    __nv_bfloat16* dh;
    __nv_bfloat16* dl;
    size_t rowoff;
    if (mat < 3) { dh = g_wqkvt_h; dl = g_wqkvt_l; rowoff = (size_t)mat * DD; }
    else         { dh = g_wot_h;   dl = g_wot_l;   rowoff = 0; }
#pragma unroll
    for (int i = 0; i < 32; i += 8) {
        float v = tile[tx][ty + i];                   // = w[k0+tx][n0+ty+i]
        __nv_bfloat16 h = __float2bfloat16(v);
        __nv_bfloat16 l = __float2bfloat16(v - __bfloat162float(h));
        size_t di = (rowoff + n0 + ty + i) * DD + k0 + tx;
        dh[di] = h;
        dl[di] = l;
    }
}

// ---------------------------------------------------------------------------
// Prep kernel C: RoPE cos/sin table
// ---------------------------------------------------------------------------
__global__ void rope_table_kernel()
{
    int s = blockIdx.x;
    int dp = threadIdx.x;    // 0..31, pair index
    float inv = expf(-0.14391156831212807f * (float)(2 * dp));
    float ang = (float)s * inv;
    float sn, cs;
    sincosf(ang, &sn, &cs);
    g_rope[s * 32 + dp] = make_float2(cs, sn);
}

// ---------------------------------------------------------------------------
// HMMA GEMM (split bf16): mode 0 = QKV+RoPE, mode 1 = out-proj.
// 3-stage cp.async pipeline, SW128-swizzled smem (no pad), 1 barrier/iter,
// pass-major MMA ordering (no back-to-back same-acc MMAs). 2 CTAs/SM.
// ---------------------------------------------------------------------------
#define ROWB 64                     // smem row bytes (32 bf16, swizzled)
#define MATB (128 * ROWB)           // 8192 bytes per matrix tile
#define STGB (4 * MATB)             // 32768 per stage
#define GEMM_SMEM_BYTES (3 * STGB)  // 98304

__global__ __launch_bounds__(256, 2) void mma_gemm_kernel(
    int mode, float* __restrict__ outp)
{
    extern __shared__ __align__(1024) char sm[];
    const uint32_t sb = smem_u32(sm);
    const int tid = threadIdx.x, wid = tid >> 5, lid = tid & 31;
    const int m0 = blockIdx.y << 7, n0 = blockIdx.x << 7;
    const int wm = wid & 1, wn = wid >> 1;

    const __nv_bfloat16* __restrict__ Ah = (mode == 0) ? g_xh : g_atth;
    const __nv_bfloat16* __restrict__ Al = (mode == 0) ? g_xl : g_attl;
    const __nv_bfloat16* __restrict__ Bh = (mode == 0) ? g_wqkvt_h : g_wot_h;
    const __nv_bfloat16* __restrict__ Bl = (mode == 0) ? g_wqkvt_l : g_wot_l;

    float acc[4][4][4];
#pragma unroll
    for (int i = 0; i < 4; i++)
#pragma unroll
        for (int j = 0; j < 4; j++)
#pragma unroll
            for (int r = 0; r < 4; r++) acc[i][j][r] = 0.f;

    const int ld_r = tid >> 2;
    const int ld_c = tid & 3;
    const uint32_t wr_off = SW(ld_r * ROWB + ld_c * 16);

    auto issue_stage = [&](int t) {
        const int k0 = t << 5;
        const uint32_t dst0 = sb + (uint32_t)(t % 3) * STGB;
#pragma unroll
        for (int q = 0; q < 4; q++) {
            const __nv_bfloat16* S = (q == 0) ? Ah : (q == 1) ? Al : (q == 2) ? Bh : Bl;
            const int rbase = (q < 2) ? m0 : n0;
#pragma unroll
            for (int half = 0; half < 2; half++) {
                // rows ld_r and ld_r+64; swizzle offset for +64 rows is
                // +64*ROWB (bits[9:7] unchanged mod pattern? recompute safely)
                int r = ld_r + half * 64;
                cp_async16(dst0 + q * MATB + SW(r * ROWB + ld_c * 16),
                           S + (size_t)(rbase + r) * DD + k0 + ld_c * 8);
            }
        }
        CP_COMMIT();
    };

    issue_stage(0);
    issue_stage(1);

    const uint32_t bg = lid >> 3, brl = lid & 7;
    const uint32_t arow = wm * 64 + (lid & 15);

    for (int t = 0; t < 32; t++) {
        if (t < 31) cp_wait<1>(); else cp_wait<0>();
        __syncthreads();
        if (t + 2 < 32) issue_stage(t + 2);

        const uint32_t stg = sb + (uint32_t)(t % 3) * STGB;
        const uint32_t sAh = stg, sAl = stg + MATB;
        const uint32_t sBh = stg + 2 * MATB, sBl = stg + 3 * MATB;

#pragma unroll
        for (int ks = 0; ks < 2; ks++) {
            uint32_t ah[4][4], al[4][4];
            const uint32_t akb = ks * 32 + ((lid & 16) ? 16 : 0);
#pragma unroll
            for (int mt = 0; mt < 4; mt++) {
                ldmatrix_x4(ah[mt], sAh + SW((arow + mt * 16) * ROWB + akb));
                ldmatrix_x4(al[mt], sAl + SW((arow + mt * 16) * ROWB + akb));
            }
            const uint32_t bkb = ks * 32 + ((bg & 1) ? 16 : 0);
#pragma unroll
            for (int p = 0; p < 2; p++) {
                const uint32_t nrow = wn * 32 + p * 16 + ((bg & 2) ? 8 : 0) + brl;
                uint32_t th[4], tl[4];
                ldmatrix_x4(th, sBh + SW(nrow * ROWB + bkb));
                ldmatrix_x4(tl, sBl + SW(nrow * ROWB + bkb));
                // pass-major: consecutive MMAs hit different accumulators
#pragma unroll
                for (int mt = 0; mt < 4; mt++) mma_bf16(acc[mt][2 * p], ah[mt], th);
#pragma unroll
                for (int mt = 0; mt < 4; mt++) mma_bf16(acc[mt][2 * p + 1], ah[mt], th + 2);
#pragma unroll
                for (int mt = 0; mt < 4; mt++) mma_bf16(acc[mt][2 * p], al[mt], th);
#pragma unroll
                for (int mt = 0; mt < 4; mt++) mma_bf16(acc[mt][2 * p + 1], al[mt], th + 2);
#pragma unroll
                for (int mt = 0; mt < 4; mt++) mma_bf16(acc[mt][2 * p], ah[mt], tl);
#pragma unroll
                for (int mt = 0; mt < 4; mt++) mma_bf16(acc[mt][2 * p + 1], ah[mt], tl + 2);
            }
        }
    }

    // Epilogue
#pragma unroll
    for (int mt = 0; mt < 4; mt++) {
#pragma unroll
        for (int nt = 0; nt < 4; nt++) {
            const int row = m0 + wm * 64 + mt * 16 + (lid >> 2);
            const int col = n0 + wn * 32 + nt * 8 + ((lid & 3) << 1);
#pragma unroll
            for (int half = 0; half < 2; half++) {
                const int r = row + half * 8;
                float v0 = acc[mt][nt][half * 2 + 0];
                float v1 = acc[mt][nt][half * 2 + 1];
                if (mode == 0) {
                    const int which = col >> 10;
                    const int nn = col & 1023;
                    const int h = nn >> 6, d = nn & 63;
                    const int b = r >> 11, s = r & 2047;
                    const size_t bh = (size_t)(b * NH + h);
                    if (which < 2) {
                        float2 cs = g_rope[s * 32 + (d >> 1)];
                        float r0 = v0 * cs.x - v1 * cs.y;
                        float r1 = v0 * cs.y + v1 * cs.x;
                        v0 = r0; v1 = r1;
                        uint32_t hi, lo;
                        split2(v0, v1, hi, lo);
                        size_t base = (bh * SS + s) * HD + d;
                        __nv_bfloat16* dh = (which == 0) ? g_qh : g_kh;
                        __nv_bfloat16* dl = (which == 0) ? g_ql : g_kl;
                        *reinterpret_cast<uint32_t*>(dh + base) = hi;
                        *reinterpret_cast<uint32_t*>(dl + base) = lo;
                    } else {
                        // V: transposed bf16 hi/lo [bh][d][s]
                        __nv_bfloat16 h0 = __float2bfloat16(v0);
                        __nv_bfloat16 h1 = __float2bfloat16(v1);
                        size_t vb = (bh * HD + d) * SS + s;
                        g_vth[vb] = h0;
                        g_vth[vb + SS] = h1;
                        g_vtl[vb] = __float2bfloat16(v0 - __bfloat162float(h0));
                        g_vtl[vb + SS] = __float2bfloat16(v1 - __bfloat162float(h1));
                    }
                } else {
                    *reinterpret_cast<float2*>(outp + (size_t)r * DD + col) =
                        make_float2(v0, v1);
                }
            }
        }
    }
}

// ---------------------------------------------------------------------------
// HMMA flash attention. CTA = 128 q rows x (b,h). 8 warps (warp = m16).
// KV tiles of 64, cp.async double-buffered. Split-bf16 for QK^T and PV.
// Rows hold HD=64 bf16 = 128 bytes -> row stride 144 bytes (pad 16).
// ---------------------------------------------------------------------------
#define AT_ROWB 144
#define AT_QB (128 * AT_ROWB)                 // 18432 per Q matrix
#define AT_KVB (64 * AT_ROWB)                 // 9216 per KV matrix
#define AT_STAGE (4 * AT_KVB)                 // 36864
#define ATT_SMEM (2 * AT_QB + 2 * AT_STAGE)   // 110592

__global__ __launch_bounds__(256, 2) void attn_mma_kernel()
{
    extern __shared__ __align__(1024) char sm[];
    const uint32_t sb = smem_u32(sm);
    const int tid = threadIdx.x, wid = tid >> 5, lid = tid & 31;
    const int qx = (int)gridDim.x - 1 - (int)blockIdx.x;  // heavy tiles first
    const int bh = blockIdx.y;
    const int q0 = qx << 7;
    const int ntiles = 2 * qx + 2;

    const __nv_bfloat16* qhp = g_qh + (size_t)bh * SS * HD;
    const __nv_bfloat16* qlp = g_ql + (size_t)bh * SS * HD;
    const __nv_bfloat16* khp = g_kh + (size_t)bh * SS * HD;
    const __nv_bfloat16* klp = g_kl + (size_t)bh * SS * HD;
    const __nv_bfloat16* vhp = g_vth + (size_t)bh * HD * SS;
    const __nv_bfloat16* vlp = g_vtl + (size_t)bh * HD * SS;

    const uint32_t sQh = sb, sQl = sb + AT_QB;
    const uint32_t sKV = sb + 2 * AT_QB;

    // Q tiles (hi+lo): 128 rows x 8 chunks of 16B each
#pragma unroll
    for (int it = 0; it < 4; it++) {
        int idx = tid + it * 256;
        int r = idx >> 3, c = idx & 7;
        cp_async16(sQh + r * AT_ROWB + c * 16, qhp + (size_t)(q0 + r) * HD + c * 8);
        cp_async16(sQl + r * AT_ROWB + c * 16, qlp + (size_t)(q0 + r) * HD + c * 8);
    }
    CP_COMMIT();

    auto issue_kv = [&](int kt) {
        const uint32_t st = sKV + (uint32_t)(kt & 1) * AT_STAGE;
        const int kv0 = kt << 6;
#pragma unroll
        for (int it = 0; it < 2; it++) {
            int idx = tid + it * 256;
            int r = idx >> 3, c = idx & 7;
            cp_async16(st + 0 * AT_KVB + r * AT_ROWB + c * 16,
                       khp + (size_t)(kv0 + r) * HD + c * 8);
            cp_async16(st + 1 * AT_KVB + r * AT_ROWB + c * 16,
                       klp + (size_t)(kv0 + r) * HD + c * 8);
            cp_async16(st + 2 * AT_KVB + r * AT_ROWB + c * 16,
                       vhp + (size_t)r * SS + kv0 + c * 8);
            cp_async16(st + 3 * AT_KVB + r * AT_ROWB + c * 16,
                       vlp + (size_t)r * SS + kv0 + c * 8);
        }
        CP_COMMIT();
    };
    issue_kv(0);

    uint32_t qfh[4][4], qfl[4][4];
    float oacc[8][4];
#pragma unroll
    for (int nt = 0; nt < 8; nt++)
#pragma unroll
        for (int e = 0; e < 4; e++) oacc[nt][e] = 0.f;
    float m0 = -INFINITY, m1 = -INFINITY, l0 = 0.f, l1 = 0.f;

    const uint32_t bg = lid >> 3, brl = lid & 7;
    const int r0 = q0 + wid * 16 + (lid >> 2);   // thread row (r1 = r0 + 8)

    for (int kt = 0; kt < ntiles; kt++) {
        if (kt + 1 < ntiles) { issue_kv(kt + 1); cp_wait<1>(); }
        else cp_wait<0>();
        __syncthreads();

        if (kt == 0) {
            const uint32_t arow = (uint32_t)(wid * 16 + (lid & 15));
            const uint32_t aoff = (lid & 16) ? 16u : 0u;
#pragma unroll
            for (int kc = 0; kc < 4; kc++) {
                ldmatrix_x4(qfh[kc], sQh + arow * AT_ROWB + kc * 32 + aoff);
                ldmatrix_x4(qfl[kc], sQl + arow * AT_ROWB + kc * 32 + aoff);
            }
        }

        const uint32_t st = sKV + (uint32_t)(kt & 1) * AT_STAGE;
        const int kv0 = kt << 6;

        // ---- S = Q K^T (split bf16); K frags per nt-pair ----
        float sacc[8][4];
#pragma unroll
        for (int nt = 0; nt < 8; nt++)
#pragma unroll
            for (int e = 0; e < 4; e++) sacc[nt][e] = 0.f;

#pragma unroll
        for (int kc = 0; kc < 4; kc++) {
            const uint32_t off = kc * 32 + ((bg & 1) ? 16 : 0);
#pragma unroll
            for (int g = 0; g < 4; g++) {
                const uint32_t nrow = g * 16 + ((bg & 2) ? 8 : 0) + brl;
                uint32_t th[4], tl[4];
                ldmatrix_x4(th, st + 0 * AT_KVB + nrow * AT_ROWB + off);
                ldmatrix_x4(tl, st + 1 * AT_KVB + nrow * AT_ROWB + off);
                mma_bf16(sacc[2 * g], qfh[kc], th);
                mma_bf16(sacc[2 * g + 1], qfh[kc], th + 2);
                mma_bf16(sacc[2 * g], qfl[kc], th);
                mma_bf16(sacc[2 * g + 1], qfl[kc], th + 2);
                mma_bf16(sacc[2 * g], qfh[kc], tl);
                mma_bf16(sacc[2 * g + 1], qfh[kc], tl + 2);
            }
        }

        // ---- scale + causal mask ----
        const bool need_mask = (kv0 + 63 > q0 + wid * 16);
#pragma unroll
        for (int nt = 0; nt < 8; nt++) {
#pragma unroll
            for (int e = 0; e < 4; e++) sacc[nt][e] *= 0.125f;
        }
        if (need_mask) {
#pragma unroll
            for (int nt = 0; nt < 8; nt++) {
                int c = kv0 + nt * 8 + ((lid & 3) << 1);
                if (c > r0)         sacc[nt][0] = -1e10f;
                if (c + 1 > r0)     sacc[nt][1] = -1e10f;
                if (c > r0 + 8)     sacc[nt][2] = -1e10f;
                if (c + 1 > r0 + 8) sacc[nt][3] = -1e10f;
            }
        }

        // ---- online softmax (rows r0, r0+8) ----
        float mx0 = -INFINITY, mx1 = -INFINITY;
#pragma unroll
        for (int nt = 0; nt < 8; nt++) {
            mx0 = fmaxf(mx0, fmaxf(sacc[nt][0], sacc[nt][1]));
            mx1 = fmaxf(mx1, fmaxf(sacc[nt][2], sacc[nt][3]));
        }
        mx0 = fmaxf(mx0, __shfl_xor_sync(0xffffffffu, mx0, 1));
        mx0 = fmaxf(mx0, __shfl_xor_sync(0xffffffffu, mx0, 2));
        mx1 = fmaxf(mx1, __shfl_xor_sync(0xffffffffu, mx1, 1));
        mx1 = fmaxf(mx1, __shfl_xor_sync(0xffffffffu, mx1, 2));
        float mn0 = fmaxf(m0, mx0), mn1 = fmaxf(m1, mx1);
        float alpha0 = __expf(m0 - mn0), alpha1 = __expf(m1 - mn1);
        float s0 = 0.f, s1 = 0.f;
#pragma unroll
        for (int nt = 0; nt < 8; nt++) {
            sacc[nt][0] = __expf(sacc[nt][0] - mn0);
            sacc[nt][1] = __expf(sacc[nt][1] - mn0);
            sacc[nt][2] = __expf(sacc[nt][2] - mn1);
            sacc[nt][3] = __expf(sacc[nt][3] - mn1);
            s0 += sacc[nt][0] + sacc[nt][1];
            s1 += sacc[nt][2] + sacc[nt][3];
        }
        s0 += __shfl_xor_sync(0xffffffffu, s0, 1);
        s0 += __shfl_xor_sync(0xffffffffu, s0, 2);
        s1 += __shfl_xor_sync(0xffffffffu, s1, 1);
        s1 += __shfl_xor_sync(0xffffffffu, s1, 2);
        l0 = l0 * alpha0 + s0;
        l1 = l1 * alpha1 + s1;
        m0 = mn0; m1 = mn1;
#pragma unroll
        for (int nt = 0; nt < 8; nt++) {
            oacc[nt][0] *= alpha0; oacc[nt][1] *= alpha0;
            oacc[nt][2] *= alpha1; oacc[nt][3] *= alpha1;
        }

        // ---- O += P V (P repacked to A-frags, split hi/lo); V per nt-pair ----
#pragma unroll
        for (int c = 0; c < 4; c++) {
            uint32_t pha[4], pla[4];
            split2(sacc[2 * c][0], sacc[2 * c][1], pha[0], pla[0]);
            split2(sacc[2 * c][2], sacc[2 * c][3], pha[1], pla[1]);
            split2(sacc[2 * c + 1][0], sacc[2 * c + 1][1], pha[2], pla[2]);
            split2(sacc[2 * c + 1][2], sacc[2 * c + 1][3], pha[3], pla[3]);

            const uint32_t off = c * 32 + ((bg & 1) ? 16 : 0);
#pragma unroll
            for (int g = 0; g < 4; g++) {
                const uint32_t nrow = g * 16 + ((bg & 2) ? 8 : 0) + brl;
                uint32_t th[4], tl[4];
                ldmatrix_x4(th, st + 2 * AT_KVB + nrow * AT_ROWB + off);
                ldmatrix_x4(tl, st + 3 * AT_KVB + nrow * AT_ROWB + off);
                mma_bf16(oacc[2 * g], pha, th);
                mma_bf16(oacc[2 * g + 1], pha, th + 2);
                mma_bf16(oacc[2 * g], pla, th);
                mma_bf16(oacc[2 * g + 1], pla, th + 2);
                mma_bf16(oacc[2 * g], pha, tl);
                mma_bf16(oacc[2 * g + 1], pha, tl + 2);
            }
        }
        __syncthreads();
    }

    // ---- epilogue: normalize, write bf16 hi/lo att ----
    const float inv0 = 1.f / l0, inv1 = 1.f / l1;
    const int b = bh >> 4, h = bh & 15;
#pragma unroll
    for (int nt = 0; nt < 8; nt++) {
        const int d = h * 64 + nt * 8 + ((lid & 3) << 1);
        uint32_t hi, lo;
        split2(oacc[nt][0] * inv0, oacc[nt][1] * inv0, hi, lo);
        size_t base0 = ((size_t)(b * SS + r0)) * DD + d;
        *reinterpret_cast<uint32_t*>(g_atth + base0) = hi;
        *reinterpret_cast<uint32_t*>(g_attl + base0) = lo;
        split2(oacc[nt][2] * inv1, oacc[nt][3] * inv1, hi, lo);
        size_t base1 = ((size_t)(b * SS + r0 + 8)) * DD + d;
        *reinterpret_cast<uint32_t*>(g_atth + base1) = hi;
        *reinterpret_cast<uint32_t*>(g_attl + base1) = lo;
    }
}

// ---------------------------------------------------------------------------
// Top-8 tiles from last token (tile-max logits — monotone w/ softmax probs)
// ---------------------------------------------------------------------------
__global__ __launch_bounds__(256) void topk_kernel(float* __restrict__ out_idx)
{
    __shared__ float qsh[64];
    __shared__ float ls[2048];
    __shared__ float tile[128];
    const int bh = blockIdx.x;
    const int tid = threadIdx.x;
    const size_t qoff = ((size_t)bh * SS + (SS - 1)) * HD;
    if (tid < 64)
        qsh[tid] = __bfloat162float(g_qh[qoff + tid]) +
                   __bfloat162float(g_ql[qoff + tid]);
    __syncthreads();
    const size_t kbase = (size_t)bh * SS * HD;
    for (int k = tid; k < SS; k += 256) {
        const uint32_t* krh = reinterpret_cast<const uint32_t*>(g_kh + kbase + (size_t)k * HD);
        const uint32_t* krl = reinterpret_cast<const uint32_t*>(g_kl + kbase + (size_t)k * HD);
        float acc = 0.f;
#pragma unroll
        for (int d2 = 0; d2 < 32; d2++) {
            uint32_t uh = krh[d2], ul = krl[d2];
            __nv_bfloat162 bh2 = *reinterpret_cast<__nv_bfloat162*>(&uh);
            __nv_bfloat162 bl2 = *reinterpret_cast<__nv_bfloat162*>(&ul);
            float k0 = __bfloat162float(bh2.x) + __bfloat162float(bl2.x);
            float k1 = __bfloat162float(bh2.y) + __bfloat162float(bl2.y);
            acc = fmaf(qsh[d2 * 2], k0, acc);
            acc = fmaf(qsh[d2 * 2 + 1], k1, acc);
        }
        ls[k] = acc;
    }
    __syncthreads();
    if (tid < 128) {
        float m = -INFINITY;
#pragma unroll
        for (int e = 0; e < 16; e++) m = fmaxf(m, ls[tid * 16 + e]);
        tile[tid] = m;
    }
    __syncthreads();
    if (tid == 0) {
        for (int slot = 0; slot < 8; slot++) {
            float best = -INFINITY; int bi = 0;
            for (int t = 0; t < 128; t++)
                if (tile[t] > best) { best = tile[t]; bi = t; }
            tile[bi] = -INFINITY;
            out_idx[bh * 8 + slot] = (float)bi;
        }
    }
}

// ---------------------------------------------------------------------------
extern "C" void kernel_launch(void* const* d_in, const int* in_sizes, int n_in,
                              void* d_out, int out_size)
{
    const float* x  = (const float*)d_in[0];
    const float* wq = (const float*)d_in[1];
    const float* wk = (const float*)d_in[2];
    const float* wv = (const float*)d_in[3];
    const float* wo = (const float*)d_in[4];
    float* out = (float*)d_out;

    cudaFuncSetAttribute(mma_gemm_kernel,
                         cudaFuncAttributeMaxDynamicSharedMemorySize, GEMM_SMEM_BYTES);
    cudaFuncSetAttribute(attn_mma_kernel,
                         cudaFuncAttributeMaxDynamicSharedMemorySize, ATT_SMEM);

    // prep
    convert_x_kernel<<<(MM * DD) / 4 / 256, 256>>>(x);
    transpose_w_kernel<<<dim3(32, 32, 4), dim3(32, 8)>>>(wq, wk, wv, wo);
    rope_table_kernel<<<SS, 32>>>();

    // QKV GEMM + RoPE (HMMA)
    mma_gemm_kernel<<<dim3(24, 32), 256, GEMM_SMEM_BYTES>>>(0, nullptr);

    // top-k tiles
    topk_kernel<<<32, 256>>>(out + (size_t)MM * DD);

    // flash attention (HMMA)
    attn_mma_kernel<<<dim3(16, 32), 256, ATT_SMEM>>>();

    // output projection (HMMA)
    mma_gemm_kernel<<<dim3(8, 32), 256, GEMM_SMEM_BYTES>>>(1, out);
}

// round 10
// speedup vs baseline: 3.0622x; 1.1781x over previous
#include <cuda_runtime.h>
#include <cuda_fp16.h>
#include <math.h>
#include <stdint.h>

#define BB 2
#define SS 2048
#define DD 1024
#define NH 16
#define HD 64
#define MM (BB*SS)

// ---------------------------------------------------------------------------
// Device scratch (allocation-free rule). Referenced ONLY from device code.
// fp16 split: value = hi + lo (11-bit mantissa each -> ~22-bit combined)
// ---------------------------------------------------------------------------
__device__ __half g_xh[(size_t)MM*DD];
__device__ __half g_xl[(size_t)MM*DD];
__device__ __half g_wqkvt_h[(size_t)3*DD*DD];   // [3072 n][1024 k]
__device__ __half g_wqkvt_l[(size_t)3*DD*DD];   // lo (used for q,k columns)
__device__ __half g_wot_h[(size_t)DD*DD];       // [1024 n][1024 k] hi only
__device__ __half g_qh[(size_t)BB*NH*SS*HD];    // [bh][s][d]
__device__ __half g_ql[(size_t)BB*NH*SS*HD];
__device__ __half g_kh[(size_t)BB*NH*SS*HD];
__device__ __half g_kl[(size_t)BB*NH*SS*HD];    // topk only
__device__ __half g_vth[(size_t)BB*NH*HD*SS];   // [bh][d][s] transposed, hi only
__device__ __half g_atth[(size_t)MM*DD];
__device__ __half g_attl[(size_t)MM*DD];
__device__ float2 g_rope[(size_t)SS*32];        // cos,sin per (s, d/2)

// ---------------------------------------------------------------------------
// PTX helpers (base ISA only — must compile for plain compute_103)
// ---------------------------------------------------------------------------
__device__ __forceinline__ uint32_t smem_u32(const void* p) {
    uint32_t a;
    asm("{ .reg .u64 t; cvta.to.shared.u64 t, %1; cvt.u32.u64 %0, t; }"
        : "=r"(a) : "l"(p));
    return a;
}
__device__ __forceinline__ void cp_async16(uint32_t dst, const void* src) {
    asm volatile("{\n .reg .u64 g;\n cvta.to.global.u64 g, %1;\n"
                 " cp.async.cg.shared.global [%0], [g], 16;\n}"
                 :: "r"(dst), "l"(src) : "memory");
}
#define CP_COMMIT() asm volatile("cp.async.commit_group;" ::: "memory")
template <int N>
__device__ __forceinline__ void cp_wait() {
    asm volatile("cp.async.wait_group %0;" :: "n"(N) : "memory");
}
__device__ __forceinline__ void ldmatrix_x4(uint32_t* r, uint32_t addr) {
    asm volatile("ldmatrix.sync.aligned.m8n8.x4.shared.b16 {%0,%1,%2,%3}, [%4];"
                 : "=r"(r[0]), "=r"(r[1]), "=r"(r[2]), "=r"(r[3]) : "r"(addr));
}
__device__ __forceinline__ void mma_f16(float* d, const uint32_t* a, const uint32_t* b) {
    asm volatile(
        "mma.sync.aligned.m16n8k16.row.col.f32.f16.f16.f32 "
        "{%0,%1,%2,%3}, {%4,%5,%6,%7}, {%8,%9}, {%0,%1,%2,%3};"
        : "+f"(d[0]), "+f"(d[1]), "+f"(d[2]), "+f"(d[3])
        : "r"(a[0]), "r"(a[1]), "r"(a[2]), "r"(a[3]), "r"(b[0]), "r"(b[1]));
}
// pack two fp32 -> fp16x2 hi + residual-lo words
__device__ __forceinline__ void split2h(float a, float b, uint32_t& hi, uint32_t& lo) {
    __half ah = __float2half_rn(a), bh = __float2half_rn(b);
    __half2 h; h.x = ah; h.y = bh;
    __half2 l;
    l.x = __float2half_rn(a - __half2float(ah));
    l.y = __float2half_rn(b - __half2float(bh));
    hi = *reinterpret_cast<uint32_t*>(&h);
    lo = *reinterpret_cast<uint32_t*>(&l);
}
// SW128 swizzle: XOR 16B-chunk index (bits[6:4]) with bits[9:7]
#define SW(off) ((uint32_t)(off) ^ (((uint32_t)(off) >> 3) & 0x70u))

// ---------------------------------------------------------------------------
// Prep kernel A: x -> fp16 hi/lo
// ---------------------------------------------------------------------------
__global__ __launch_bounds__(256) void convert_x_kernel(const float* __restrict__ x)
{
    size_t idx = (size_t)blockIdx.x * 256 + threadIdx.x;   // one float4
    float4 v = reinterpret_cast<const float4*>(x)[idx];
    uint32_t h0, l0, h1, l1;
    split2h(v.x, v.y, h0, l0);
    split2h(v.z, v.w, h1, l1);
    reinterpret_cast<uint32_t*>(g_xh)[idx * 2 + 0] = h0;
    reinterpret_cast<uint32_t*>(g_xh)[idx * 2 + 1] = h1;
    reinterpret_cast<uint32_t*>(g_xl)[idx * 2 + 0] = l0;
    reinterpret_cast<uint32_t*>(g_xl)[idx * 2 + 1] = l1;
}

// ---------------------------------------------------------------------------
// Prep kernel B: transpose weights -> N-major fp16 (hi always, lo for wq/wk/wv)
// ---------------------------------------------------------------------------
__global__ __launch_bounds__(256) void transpose_w_kernel(
    const float* __restrict__ wq, const float* __restrict__ wk,
    const float* __restrict__ wv, const float* __restrict__ wo)
{
    __shared__ float tile[32][33];
    const int mat = blockIdx.z;
    const float* src = (mat == 0) ? wq : (mat == 1) ? wk : (mat == 2) ? wv : wo;
    const int k0 = blockIdx.y * 32, n0 = blockIdx.x * 32;
    const int tx = threadIdx.x, ty = threadIdx.y;     // 32 x 8
#pragma unroll
    for (int i = 0; i < 32; i += 8)
        tile[ty + i][tx] = src[(size_t)(k0 + ty + i) * DD + n0 + tx];
    __syncthreads();
#pragma unroll
    for (int i = 0; i < 32; i += 8) {
        float v = tile[tx][ty + i];                   // = w[k0+tx][n0+ty+i]
        __half h = __float2half_rn(v);
        if (mat < 3) {
            size_t di = ((size_t)mat * DD + n0 + ty + i) * DD + k0 + tx;
            g_wqkvt_h[di] = h;
            g_wqkvt_l[di] = __float2half_rn(v - __half2float(h));
        } else {
            g_wot_h[(size_t)(n0 + ty + i) * DD + k0 + tx] = h;
        }
    }
}

// ---------------------------------------------------------------------------
// Prep kernel C: RoPE cos/sin table
// ---------------------------------------------------------------------------
__global__ void rope_table_kernel()
{
    int s = blockIdx.x;
    int dp = threadIdx.x;    // 0..31, pair index
    float inv = expf(-0.14391156831212807f * (float)(2 * dp));
    float ang = (float)s * inv;
    float sn, cs;
    sincosf(ang, &sn, &cs);
    g_rope[s * 32 + dp] = make_float2(cs, sn);
}

// ---------------------------------------------------------------------------
// HMMA GEMM (fp16 split).
//   q,k columns (mode 0, n0 < 2048): 3-term  Ah*Bh + Al*Bh + Ah*Bl
//   v columns & out-proj:            2-term  Ah*Bh + Al*Bh
// 3-stage cp.async pipeline, SW128 swizzle, 1 barrier/iter. 2 CTAs/SM.
// ---------------------------------------------------------------------------
#define ROWB 64                     // smem row bytes (32 fp16, swizzled)
#define MATB (128 * ROWB)           // 8192 bytes per matrix tile
#define STGB (4 * MATB)             // 32768 per stage (Ah, Al, Bh, Bl)
#define GEMM_SMEM_BYTES (3 * STGB)  // 98304

__global__ __launch_bounds__(256, 2) void mma_gemm_kernel(
    int mode, float* __restrict__ outp)
{
    extern __shared__ __align__(1024) char sm[];
    const uint32_t sb = smem_u32(sm);
    const int tid = threadIdx.x, wid = tid >> 5, lid = tid & 31;
    const int m0 = blockIdx.y << 7, n0 = blockIdx.x << 7;
    const int wm = wid & 1, wn = wid >> 1;
    const bool third = (mode == 0) && (n0 < 2048);   // q,k need 3rd term

    const __half* __restrict__ Ah = (mode == 0) ? g_xh : g_atth;
    const __half* __restrict__ Al = (mode == 0) ? g_xl : g_attl;
    const __half* __restrict__ Bh = (mode == 0) ? g_wqkvt_h : g_wot_h;
    const __half* __restrict__ Bl = g_wqkvt_l;       // only read when third

    float acc[4][4][4];
#pragma unroll
    for (int i = 0; i < 4; i++)
#pragma unroll
        for (int j = 0; j < 4; j++)
#pragma unroll
            for (int r = 0; r < 4; r++) acc[i][j][r] = 0.f;

    const int ld_r = tid >> 2;
    const int ld_c = tid & 3;

    auto issue_stage = [&](int t) {
        const int k0 = t << 5;
        const uint32_t dst0 = sb + (uint32_t)(t % 3) * STGB;
#pragma unroll
        for (int q = 0; q < 3; q++) {
            const __half* S = (q == 0) ? Ah : (q == 1) ? Al : Bh;
            const int rbase = (q < 2) ? m0 : n0;
#pragma unroll
            for (int half = 0; half < 2; half++) {
                int r = ld_r + half * 64;
                cp_async16(dst0 + q * MATB + SW(r * ROWB + ld_c * 16),
                           S + (size_t)(rbase + r) * DD + k0 + ld_c * 8);
            }
        }
        if (third) {
#pragma unroll
            for (int half = 0; half < 2; half++) {
                int r = ld_r + half * 64;
                cp_async16(dst0 + 3 * MATB + SW(r * ROWB + ld_c * 16),
                           Bl + (size_t)(n0 + r) * DD + k0 + ld_c * 8);
            }
        }
        CP_COMMIT();
    };

    issue_stage(0);
    issue_stage(1);

    const uint32_t bg = lid >> 3, brl = lid & 7;
    const uint32_t arow = wm * 64 + (lid & 15);

    for (int t = 0; t < 32; t++) {
        if (t < 31) cp_wait<1>(); else cp_wait<0>();
        __syncthreads();
        if (t + 2 < 32) issue_stage(t + 2);

        const uint32_t stg = sb + (uint32_t)(t % 3) * STGB;
        const uint32_t sAh = stg, sAl = stg + MATB;
        const uint32_t sBh = stg + 2 * MATB, sBl = stg + 3 * MATB;

#pragma unroll
        for (int ks = 0; ks < 2; ks++) {
            uint32_t ah[4][4], al[4][4];
            const uint32_t akb = ks * 32 + ((lid & 16) ? 16 : 0);
#pragma unroll
            for (int mt = 0; mt < 4; mt++) {
                ldmatrix_x4(ah[mt], sAh + SW((arow + mt * 16) * ROWB + akb));
                ldmatrix_x4(al[mt], sAl + SW((arow + mt * 16) * ROWB + akb));
            }
            const uint32_t bkb = ks * 32 + ((bg & 1) ? 16 : 0);
#pragma unroll
            for (int p = 0; p < 2; p++) {
                const uint32_t nrow = wn * 32 + p * 16 + ((bg & 2) ? 8 : 0) + brl;
                uint32_t th[4];
                ldmatrix_x4(th, sBh + SW(nrow * ROWB + bkb));
                // pass-major: consecutive MMAs hit different accumulators
#pragma unroll
                for (int mt = 0; mt < 4; mt++) mma_f16(acc[mt][2 * p], ah[mt], th);
#pragma unroll
                for (int mt = 0; mt < 4; mt++) mma_f16(acc[mt][2 * p + 1], ah[mt], th + 2);
#pragma unroll
                for (int mt = 0; mt < 4; mt++) mma_f16(acc[mt][2 * p], al[mt], th);
#pragma unroll
                for (int mt = 0; mt < 4; mt++) mma_f16(acc[mt][2 * p + 1], al[mt], th + 2);
                if (third) {
                    uint32_t tl[4];
                    ldmatrix_x4(tl, sBl + SW(nrow * ROWB + bkb));
#pragma unroll
                    for (int mt = 0; mt < 4; mt++) mma_f16(acc[mt][2 * p], ah[mt], tl);
#pragma unroll
                    for (int mt = 0; mt < 4; mt++) mma_f16(acc[mt][2 * p + 1], ah[mt], tl + 2);
                }
            }
        }
    }

    // Epilogue
#pragma unroll
    for (int mt = 0; mt < 4; mt++) {
#pragma unroll
        for (int nt = 0; nt < 4; nt++) {
            const int row = m0 + wm * 64 + mt * 16 + (lid >> 2);
            const int col = n0 + wn * 32 + nt * 8 + ((lid & 3) << 1);
#pragma unroll
            for (int half = 0; half < 2; half++) {
                const int r = row + half * 8;
                float v0 = acc[mt][nt][half * 2 + 0];
                float v1 = acc[mt][nt][half * 2 + 1];
                if (mode == 0) {
                    const int which = col >> 10;
                    const int nn = col & 1023;
                    const int h = nn >> 6, d = nn & 63;
                    const int b = r >> 11, s = r & 2047;
                    const size_t bh = (size_t)(b * NH + h);
                    if (which < 2) {
                        float2 cs = g_rope[s * 32 + (d >> 1)];
                        float r0 = v0 * cs.x - v1 * cs.y;
                        float r1 = v0 * cs.y + v1 * cs.x;
                        v0 = r0; v1 = r1;
                        uint32_t hi, lo;
                        split2h(v0, v1, hi, lo);
                        size_t base = (bh * SS + s) * HD + d;
                        __half* dh = (which == 0) ? g_qh : g_kh;
                        __half* dl = (which == 0) ? g_ql : g_kl;
                        *reinterpret_cast<uint32_t*>(dh + base) = hi;
                        *reinterpret_cast<uint32_t*>(dl + base) = lo;
                    } else {
                        // V: transposed fp16 hi [bh][d][s]
                        size_t vb = (bh * HD + d) * SS + s;
                        g_vth[vb] = __float2half_rn(v0);
                        g_vth[vb + SS] = __float2half_rn(v1);
                    }
                } else {
                    *reinterpret_cast<float2*>(outp + (size_t)r * DD + col) =
                        make_float2(v0, v1);
                }
            }
        }
    }
}

// ---------------------------------------------------------------------------
// HMMA flash attention (fp16 2-term: S = Qh*Kh + Ql*Kh; O += Ph*Vh + Pl*Vh).
// CTA = 128 q rows x (b,h). 8 warps. KV tiles of 64, 3-stage cp.async.
// ---------------------------------------------------------------------------
#define AT_ROWB 144
#define AT_QB (128 * AT_ROWB)                 // 18432 per Q matrix
#define AT_KVB (64 * AT_ROWB)                 // 9216 per KV matrix
#define AT_STAGE (2 * AT_KVB)                 // 18432 (Kh + Vh)
#define ATT_SMEM (2 * AT_QB + 3 * AT_STAGE)   // 92160

__global__ __launch_bounds__(256, 2) void attn_mma_kernel()
{
    extern __shared__ __align__(1024) char sm[];
    const uint32_t sb = smem_u32(sm);
    const int tid = threadIdx.x, wid = tid >> 5, lid = tid & 31;
    const int qx = (int)gridDim.x - 1 - (int)blockIdx.x;  // heavy tiles first
    const int bh = blockIdx.y;
    const int q0 = qx << 7;
    const int ntiles = 2 * qx + 2;

    const __half* qhp = g_qh + (size_t)bh * SS * HD;
    const __half* qlp = g_ql + (size_t)bh * SS * HD;
    const __half* khp = g_kh + (size_t)bh * SS * HD;
    const __half* vhp = g_vth + (size_t)bh * HD * SS;

    const uint32_t sQh = sb, sQl = sb + AT_QB;
    const uint32_t sKV = sb + 2 * AT_QB;

    // Q tiles (hi+lo): 128 rows x 8 chunks of 16B each (group 0)
#pragma unroll
    for (int it = 0; it < 4; it++) {
        int idx = tid + it * 256;
        int r = idx >> 3, c = idx & 7;
        cp_async16(sQh + r * AT_ROWB + c * 16, qhp + (size_t)(q0 + r) * HD + c * 8);
        cp_async16(sQl + r * AT_ROWB + c * 16, qlp + (size_t)(q0 + r) * HD + c * 8);
    }
    CP_COMMIT();

    auto issue_kv = [&](int kt) {
        const uint32_t st = sKV + (uint32_t)(kt % 3) * AT_STAGE;
        const int kv0 = kt << 6;
#pragma unroll
        for (int it = 0; it < 2; it++) {
            int idx = tid + it * 256;
            int r = idx >> 3, c = idx & 7;
            cp_async16(st + 0 * AT_KVB + r * AT_ROWB + c * 16,
                       khp + (size_t)(kv0 + r) * HD + c * 8);
            cp_async16(st + 1 * AT_KVB + r * AT_ROWB + c * 16,
                       vhp + (size_t)r * SS + kv0 + c * 8);
        }
        CP_COMMIT();
    };
    issue_kv(0);
    issue_kv(1);

    uint32_t qfh[4][4], qfl[4][4];
    float oacc[8][4];
#pragma unroll
    for (int nt = 0; nt < 8; nt++)
#pragma unroll
        for (int e = 0; e < 4; e++) oacc[nt][e] = 0.f;
    float m0 = -INFINITY, m1 = -INFINITY, l0 = 0.f, l1 = 0.f;

    const uint32_t bg = lid >> 3, brl = lid & 7;
    const int r0 = q0 + wid * 16 + (lid >> 2);   // thread row (r1 = r0 + 8)

    for (int kt = 0; kt < ntiles; kt++) {
        if (kt + 1 < ntiles) cp_wait<1>(); else cp_wait<0>();
        __syncthreads();
        if (kt + 2 < ntiles) issue_kv(kt + 2);

        if (kt == 0) {
            const uint32_t arow = (uint32_t)(wid * 16 + (lid & 15));
            const uint32_t aoff = (lid & 16) ? 16u : 0u;
#pragma unroll
            for (int kc = 0; kc < 4; kc++) {
                ldmatrix_x4(qfh[kc], sQh + arow * AT_ROWB + kc * 32 + aoff);
                ldmatrix_x4(qfl[kc], sQl + arow * AT_ROWB + kc * 32 + aoff);
            }
        }

        const uint32_t st = sKV + (uint32_t)(kt % 3) * AT_STAGE;
        const int kv0 = kt << 6;

        // ---- S = Q K^T (fp16 2-term) ----
        float sacc[8][4];
#pragma unroll
        for (int nt = 0; nt < 8; nt++)
#pragma unroll
            for (int e = 0; e < 4; e++) sacc[nt][e] = 0.f;

#pragma unroll
        for (int kc = 0; kc < 4; kc++) {
            const uint32_t off = kc * 32 + ((bg & 1) ? 16 : 0);
#pragma unroll
            for (int g = 0; g < 4; g++) {
                const uint32_t nrow = g * 16 + ((bg & 2) ? 8 : 0) + brl;
                uint32_t th[4];
                ldmatrix_x4(th, st + 0 * AT_KVB + nrow * AT_ROWB + off);
                mma_f16(sacc[2 * g], qfh[kc], th);
                mma_f16(sacc[2 * g + 1], qfh[kc], th + 2);
                mma_f16(sacc[2 * g], qfl[kc], th);
                mma_f16(sacc[2 * g + 1], qfl[kc], th + 2);
            }
        }

        // ---- scale + causal mask ----
        const bool need_mask = (kv0 + 63 > q0 + wid * 16);
#pragma unroll
        for (int nt = 0; nt < 8; nt++) {
#pragma unroll
            for (int e = 0; e < 4; e++) sacc[nt][e] *= 0.125f;
        }
        if (need_mask) {
#pragma unroll
            for (int nt = 0; nt < 8; nt++) {
                int c = kv0 + nt * 8 + ((lid & 3) << 1);
                if (c > r0)         sacc[nt][0] = -1e10f;
                if (c + 1 > r0)     sacc[nt][1] = -1e10f;
                if (c > r0 + 8)     sacc[nt][2] = -1e10f;
                if (c + 1 > r0 + 8) sacc[nt][3] = -1e10f;
            }
        }

        // ---- online softmax (rows r0, r0+8) ----
        float mx0 = -INFINITY, mx1 = -INFINITY;
#pragma unroll
        for (int nt = 0; nt < 8; nt++) {
            mx0 = fmaxf(mx0, fmaxf(sacc[nt][0], sacc[nt][1]));
            mx1 = fmaxf(mx1, fmaxf(sacc[nt][2], sacc[nt][3]));
        }
        mx0 = fmaxf(mx0, __shfl_xor_sync(0xffffffffu, mx0, 1));
        mx0 = fmaxf(mx0, __shfl_xor_sync(0xffffffffu, mx0, 2));
        mx1 = fmaxf(mx1, __shfl_xor_sync(0xffffffffu, mx1, 1));
        mx1 = fmaxf(mx1, __shfl_xor_sync(0xffffffffu, mx1, 2));
        float mn0 = fmaxf(m0, mx0), mn1 = fmaxf(m1, mx1);
        float alpha0 = __expf(m0 - mn0), alpha1 = __expf(m1 - mn1);
        float s0 = 0.f, s1 = 0.f;
#pragma unroll
        for (int nt = 0; nt < 8; nt++) {
            sacc[nt][0] = __expf(sacc[nt][0] - mn0);
            sacc[nt][1] = __expf(sacc[nt][1] - mn0);
            sacc[nt][2] = __expf(sacc[nt][2] - mn1);
            sacc[nt][3] = __expf(sacc[nt][3] - mn1);
            s0 += sacc[nt][0] + sacc[nt][1];
            s1 += sacc[nt][2] + sacc[nt][3];
        }
        s0 += __shfl_xor_sync(0xffffffffu, s0, 1);
        s0 += __shfl_xor_sync(0xffffffffu, s0, 2);
        s1 += __shfl_xor_sync(0xffffffffu, s1, 1);
        s1 += __shfl_xor_sync(0xffffffffu, s1, 2);
        l0 = l0 * alpha0 + s0;
        l1 = l1 * alpha1 + s1;
        m0 = mn0; m1 = mn1;
#pragma unroll
        for (int nt = 0; nt < 8; nt++) {
            oacc[nt][0] *= alpha0; oacc[nt][1] *= alpha0;
            oacc[nt][2] *= alpha1; oacc[nt][3] *= alpha1;
        }

        // ---- O += P V (P split hi/lo fp16, V hi) ----
#pragma unroll
        for (int c = 0; c < 4; c++) {
            uint32_t pha[4], pla[4];
            split2h(sacc[2 * c][0], sacc[2 * c][1], pha[0], pla[0]);
            split2h(sacc[2 * c][2], sacc[2 * c][3], pha[1], pla[1]);
            split2h(sacc[2 * c + 1][0], sacc[2 * c + 1][1], pha[2], pla[2]);
            split2h(sacc[2 * c + 1][2], sacc[2 * c + 1][3], pha[3], pla[3]);

            const uint32_t off = c * 32 + ((bg & 1) ? 16 : 0);
#pragma unroll
            for (int g = 0; g < 4; g++) {
                const uint32_t nrow = g * 16 + ((bg & 2) ? 8 : 0) + brl;
                uint32_t th[4];
                ldmatrix_x4(th, st + 1 * AT_KVB + nrow * AT_ROWB + off);
                mma_f16(oacc[2 * g], pha, th);
                mma_f16(oacc[2 * g + 1], pha, th + 2);
                mma_f16(oacc[2 * g], pla, th);
                mma_f16(oacc[2 * g + 1], pla, th + 2);
            }
        }
    }

    // ---- epilogue: normalize, write fp16 hi/lo att ----
    const float inv0 = 1.f / l0, inv1 = 1.f / l1;
    const int b = bh >> 4, h = bh & 15;
#pragma unroll
    for (int nt = 0; nt < 8; nt++) {
        const int d = h * 64 + nt * 8 + ((lid & 3) << 1);
        uint32_t hi, lo;
        split2h(oacc[nt][0] * inv0, oacc[nt][1] * inv0, hi, lo);
        size_t base0 = ((size_t)(b * SS + r0)) * DD + d;
        *reinterpret_cast<uint32_t*>(g_atth + base0) = hi;
        *reinterpret_cast<uint32_t*>(g_attl + base0) = lo;
        split2h(oacc[nt][2] * inv1, oacc[nt][3] * inv1, hi, lo);
        size_t base1 = ((size_t)(b * SS + r0 + 8)) * DD + d;
        *reinterpret_cast<uint32_t*>(g_atth + base1) = hi;
        *reinterpret_cast<uint32_t*>(g_attl + base1) = lo;
    }
}

// ---------------------------------------------------------------------------
// Top-8 tiles from last token (tile-max logits — monotone w/ softmax probs)
// q,k now accurate to ~2^-22 (3-term GEMM); hi+lo reconstruction keeps ranking.
// ---------------------------------------------------------------------------
__global__ __launch_bounds__(256) void topk_kernel(float* __restrict__ out_idx)
{
    __shared__ float qsh[64];
    __shared__ float ls[2048];
    __shared__ float tile[128];
    const int bh = blockIdx.x;
    const int tid = threadIdx.x;
    const size_t qoff = ((size_t)bh * SS + (SS - 1)) * HD;
    if (tid < 64)
        qsh[tid] = __half2float(g_qh[qoff + tid]) +
                   __half2float(g_ql[qoff + tid]);
    __syncthreads();
    const size_t kbase = (size_t)bh * SS * HD;
    for (int k = tid; k < SS; k += 256) {
        const uint32_t* krh = reinterpret_cast<const uint32_t*>(g_kh + kbase + (size_t)k * HD);
        const uint32_t* krl = reinterpret_cast<const uint32_t*>(g_kl + kbase + (size_t)k * HD);
        float acc = 0.f;
#pragma unroll
        for (int d2 = 0; d2 < 32; d2++) {
            uint32_t uh = krh[d2], ul = krl[d2];
            __half2 hh = *reinterpret_cast<__half2*>(&uh);
            __half2 hl = *reinterpret_cast<__half2*>(&ul);
            float k0 = __half2float(hh.x) + __half2float(hl.x);
            float k1 = __half2float(hh.y) + __half2float(hl.y);
            acc = fmaf(qsh[d2 * 2], k0, acc);
            acc = fmaf(qsh[d2 * 2 + 1], k1, acc);
        }
        ls[k] = acc;
    }
    __syncthreads();
    if (tid < 128) {
        float m = -INFINITY;
#pragma unroll
        for (int e = 0; e < 16; e++) m = fmaxf(m, ls[tid * 16 + e]);
        tile[tid] = m;
    }
    __syncthreads();
    if (tid == 0) {
        for (int slot = 0; slot < 8; slot++) {
            float best = -INFINITY; int bi = 0;
            for (int t = 0; t < 128; t++)
                if (tile[t] > best) { best = tile[t]; bi = t; }
            tile[bi] = -INFINITY;
            out_idx[bh * 8 + slot] = (float)bi;
        }
    }
}

// ---------------------------------------------------------------------------
extern "C" void kernel_launch(void* const* d_in, const int* in_sizes, int n_in,
                              void* d_out, int out_size)
{
    const float* x  = (const float*)d_in[0];
    const float* wq = (const float*)d_in[1];
    const float* wk = (const float*)d_in[2];
    const float* wv = (const float*)d_in[3];
    const float* wo = (const float*)d_in[4];
    float* out = (float*)d_out;

    cudaFuncSetAttribute(mma_gemm_kernel,
                         cudaFuncAttributeMaxDynamicSharedMemorySize, GEMM_SMEM_BYTES);
    cudaFuncSetAttribute(attn_mma_kernel,
                         cudaFuncAttributeMaxDynamicSharedMemorySize, ATT_SMEM);

    // prep
    convert_x_kernel<<<(MM * DD) / 4 / 256, 256>>>(x);
    transpose_w_kernel<<<dim3(32, 32, 4), dim3(32, 8)>>>(wq, wk, wv, wo);
    rope_table_kernel<<<SS, 32>>>();

    // QKV GEMM + RoPE (HMMA)
    mma_gemm_kernel<<<dim3(24, 32), 256, GEMM_SMEM_BYTES>>>(0, nullptr);

    // top-k tiles
    topk_kernel<<<32, 256>>>(out + (size_t)MM * DD);

    // flash attention (HMMA)
    attn_mma_kernel<<<dim3(16, 32), 256, ATT_SMEM>>>();

    // output projection (HMMA)
    mma_gemm_kernel<<<dim3(8, 32), 256, GEMM_SMEM_BYTES>>>(1, out);
}